// round 2
// baseline (speedup 1.0000x reference)
#include <cuda_runtime.h>
#include <math.h>

// Problem constants
#define Bc   8
#define Nc   512
#define Tc   64
#define NINc 64
#define NHc  128
#define Rc   (Bc * Nc)   // 4096 rows

// ---------------- scratch (device globals) ----------------------------------
__device__ float g_dinv[Rc];
__device__ float g_An[Bc * Nc * Nc];        // 8 MB normalized adjacency
__device__ float g_es[Rc * NHc];            // static embedding (128 wide)
__device__ float g_h[2][Rc * NHc];          // double-buffered hidden
__device__ float g_c[Rc * NHc];             // cell state
__device__ float g_Hagg[Rc * NHc];          // H = An @ h
__device__ float g_Xi[Rc * NINc];           // running output accumulator
__device__ float g_Wcomb[256 * 512];        // k<128: Wpe@Wi2 ; k>=128: Wh  (cols interleaved j*4+g)
__device__ float g_Wes[128 * 512];          // Wi[0:128] interleaved
__device__ float g_Ges[Rc * 512];           // es @ Wes + bias (precomputed, interleaved)
__device__ float g_bbig[512];

// ---------------- f32x2 helpers ---------------------------------------------
__device__ __forceinline__ unsigned long long pack2(float x) {
    unsigned long long r;
    asm("mov.b64 %0, {%1, %1};" : "=l"(r) : "f"(x));
    return r;
}
__device__ __forceinline__ void fma2(unsigned long long& d, unsigned long long a, unsigned long long b) {
    asm("fma.rn.f32x2 %0, %1, %2, %0;" : "+l"(d) : "l"(a), "l"(b));
}
__device__ __forceinline__ float2 up2(unsigned long long v) {
    float2 f;
    asm("mov.b64 {%0, %1}, %2;" : "=f"(f.x), "=f"(f.y) : "l"(v));
    return f;
}
__device__ __forceinline__ float sigm(float x) { return 1.f / (1.f + expf(-x)); }

// ---------------------------------------------------------------------------
__global__ void k_dinv(const float* __restrict__ A) {
    int row = blockIdx.x;
    const float* arow = A + (size_t)row * Nc;
    float s = 0.f;
    for (int j = threadIdx.x; j < Nc; j += blockDim.x) s += arow[j];
    __shared__ float sh[128];
    sh[threadIdx.x] = s;
    __syncthreads();
    for (int off = 64; off > 0; off >>= 1) {
        if (threadIdx.x < off) sh[threadIdx.x] += sh[threadIdx.x + off];
        __syncthreads();
    }
    if (threadIdx.x == 0) {
        float d = sh[0];
        g_dinv[row] = (d > 0.f) ? rsqrtf(d) : 0.f;
    }
}

__global__ void k_an(const float* __restrict__ A) {
    int idx = blockIdx.x * blockDim.x + threadIdx.x;
    int e = idx * 4;
    int b   = e >> 18;
    int rem = e & 262143;
    int i   = rem >> 9;
    int j   = rem & 511;
    float4 a = *(const float4*)(A + (size_t)e);
    float di = g_dinv[b * 512 + i];
    const float* dj = g_dinv + b * 512 + j;
    a.x *= di * dj[0]; a.y *= di * dj[1]; a.z *= di * dj[2]; a.w *= di * dj[3];
    *(float4*)(g_An + (size_t)e) = a;
}

// ---------------------------------------------------------------------------
// Build Wcomb / Wes / bbig with interleaved column layout n = j*4 + g.
// ---------------------------------------------------------------------------
__global__ void k_prep(const float* __restrict__ Wii, const float* __restrict__ bii,
                       const float* __restrict__ Whi, const float* __restrict__ bhi,
                       const float* __restrict__ Wif, const float* __restrict__ bif_,
                       const float* __restrict__ Whf, const float* __restrict__ bhf,
                       const float* __restrict__ Wig, const float* __restrict__ big_,
                       const float* __restrict__ Whg, const float* __restrict__ bhg,
                       const float* __restrict__ Wio, const float* __restrict__ bio,
                       const float* __restrict__ Who, const float* __restrict__ bho,
                       const float* __restrict__ Wpe, const float* __restrict__ bpe) {
    int n = blockIdx.x;
    int g = n & 3;
    int j = n >> 2;
    int t = threadIdx.x;
    const float* Wi = (g == 0) ? Wii : (g == 1) ? Wif : (g == 2) ? Wig : Wio;
    const float* Wh = (g == 0) ? Whi : (g == 1) ? Whf : (g == 2) ? Whg : Who;
    const float* bi = (g == 0) ? bii : (g == 1) ? bif_ : (g == 2) ? big_ : bio;
    const float* bh = (g == 0) ? bhi : (g == 1) ? bhf : (g == 2) ? bhg : bho;

    __shared__ float wcol[128];
    wcol[t] = Wi[(128 + t) * 128 + j];
    __syncthreads();

    g_Wes[t * 512 + n]           = Wi[t * 128 + j];
    g_Wcomb[(128 + t) * 512 + n] = Wh[t * 128 + j];

    float acc = 0.f;
    const float* wpet = Wpe + t * 128;
#pragma unroll 8
    for (int m = 0; m < 128; m++) acc += wpet[m] * wcol[m];
    g_Wcomb[t * 512 + n] = acc;

    if (t == 0) {
        float ba = bi[j] + bh[j];
        for (int m = 0; m < 128; m++) ba += bpe[m] * wcol[m];
        g_bbig[n] = ba;
    }
}

// ---------------------------------------------------------------------------
// Init: es = X0 @ Wse + bse ; h0 = c0 = 0 ; Xi = X0 ; out[:, :, 0, :] = X0
// ---------------------------------------------------------------------------
__global__ void k_init(const float* __restrict__ X, const float* __restrict__ Wse,
                       const float* __restrict__ bse, float* __restrict__ out) {
    int row = blockIdx.x;
    int t = threadIdx.x;
    __shared__ float x0[64];
    if (t < 64) {
        float v = X[(size_t)row * 4096 + t];
        x0[t] = v;
        g_Xi[row * 64 + t] = v;
        out[(size_t)row * 4096 + t] = v;
    }
    __syncthreads();
    float acc = bse[t];
#pragma unroll 8
    for (int k = 0; k < 64; k++) acc += x0[k] * Wse[k * 128 + t];
    g_es[row * 128 + t] = acc;
    g_h[0][(size_t)row * 128 + t] = 0.f;
    g_c[row * 128 + t] = 0.f;
}

// ---------------------------------------------------------------------------
// k_ges: Ges = es @ Wes + bbig   (4096 x 512, K=128), tile 64x128, f32x2 inner
// grid = 64 mtiles * 4 ntiles = 256 blocks, 256 threads
// ---------------------------------------------------------------------------
__global__ void __launch_bounds__(256) k_ges() {
    int m0 = (blockIdx.x >> 2) * 64;
    int n0 = (blockIdx.x & 3) * 128;

    __shared__ __align__(16) float As[2][16][68];
    __shared__ __align__(16) float Bs[2][16][132];

    int tid = threadIdx.x;
    int ty = tid >> 4, tx = tid & 15;
    int ar = tid >> 2, ac = (tid & 3) * 4;
    int br = tid >> 5, bc = (tid & 31) * 4;

    unsigned long long acc[4][4];
#pragma unroll
    for (int i = 0; i < 4; i++)
#pragma unroll
        for (int j = 0; j < 4; j++) acc[i][j] = 0ull;

    float4 av = *(const float4*)&g_es[(size_t)(m0 + ar) * 128 + ac];
    float4 bv0 = *(const float4*)&g_Wes[(size_t)br * 512 + n0 + bc];
    float4 bv1 = *(const float4*)&g_Wes[(size_t)(br + 8) * 512 + n0 + bc];
    As[0][ac + 0][ar] = av.x; As[0][ac + 1][ar] = av.y;
    As[0][ac + 2][ar] = av.z; As[0][ac + 3][ar] = av.w;
    *(float4*)&Bs[0][br][bc] = bv0;
    *(float4*)&Bs[0][br + 8][bc] = bv1;
    __syncthreads();

    int buf = 0;
    for (int c = 0; c < 8; c++) {
        if (c + 1 < 8) {
            int k0 = (c + 1) * 16;
            av  = *(const float4*)&g_es[(size_t)(m0 + ar) * 128 + k0 + ac];
            bv0 = *(const float4*)&g_Wes[(size_t)(k0 + br) * 512 + n0 + bc];
            bv1 = *(const float4*)&g_Wes[(size_t)(k0 + br + 8) * 512 + n0 + bc];
        }
#pragma unroll
        for (int kk = 0; kk < 16; kk++) {
            float4 a4 = *(const float4*)&As[buf][kk][ty * 4];
            unsigned long long a0 = pack2(a4.x), a1 = pack2(a4.y),
                               a2 = pack2(a4.z), a3 = pack2(a4.w);
            ulonglong2 b01 = *(const ulonglong2*)&Bs[buf][kk][tx * 8];
            ulonglong2 b23 = *(const ulonglong2*)&Bs[buf][kk][tx * 8 + 4];
            fma2(acc[0][0], a0, b01.x); fma2(acc[0][1], a0, b01.y);
            fma2(acc[0][2], a0, b23.x); fma2(acc[0][3], a0, b23.y);
            fma2(acc[1][0], a1, b01.x); fma2(acc[1][1], a1, b01.y);
            fma2(acc[1][2], a1, b23.x); fma2(acc[1][3], a1, b23.y);
            fma2(acc[2][0], a2, b01.x); fma2(acc[2][1], a2, b01.y);
            fma2(acc[2][2], a2, b23.x); fma2(acc[2][3], a2, b23.y);
            fma2(acc[3][0], a3, b01.x); fma2(acc[3][1], a3, b01.y);
            fma2(acc[3][2], a3, b23.x); fma2(acc[3][3], a3, b23.y);
        }
        if (c + 1 < 8) {
            buf ^= 1;
            As[buf][ac + 0][ar] = av.x; As[buf][ac + 1][ar] = av.y;
            As[buf][ac + 2][ar] = av.z; As[buf][ac + 3][ar] = av.w;
            *(float4*)&Bs[buf][br][bc] = bv0;
            *(float4*)&Bs[buf][br + 8][bc] = bv1;
            __syncthreads();
        }
    }

    float4 bb0 = *(const float4*)&g_bbig[n0 + tx * 8];
    float4 bb1 = *(const float4*)&g_bbig[n0 + tx * 8 + 4];
#pragma unroll
    for (int r = 0; r < 4; r++) {
        int rr = m0 + ty * 4 + r;
        float2 t0 = up2(acc[r][0]), t1 = up2(acc[r][1]),
               t2 = up2(acc[r][2]), t3 = up2(acc[r][3]);
        float4 v0 = make_float4(t0.x + bb0.x, t0.y + bb0.y, t1.x + bb0.z, t1.y + bb0.w);
        float4 v1 = make_float4(t2.x + bb1.x, t2.y + bb1.y, t3.x + bb1.z, t3.y + bb1.w);
        float* dst = &g_Ges[(size_t)rr * 512 + n0 + tx * 8];
        *(float4*)dst = v0;
        *(float4*)(dst + 4) = v1;
    }
}

// ---------------------------------------------------------------------------
// H = An @ h_prev   (per batch 512x512 @ 512x128), tile 32x128, f32x2 inner
// grid = 8 batches * 16 mtiles = 128 blocks, 256 threads
// ---------------------------------------------------------------------------
__global__ void __launch_bounds__(256) k_gemmH(int hin) {
    int b  = blockIdx.x >> 4;
    int m0 = (blockIdx.x & 15) * 32;
    const float* __restrict__ Ab = g_An + (size_t)b * Nc * Nc;
    const float* __restrict__ Bb = g_h[hin] + (size_t)b * Nc * NHc;

    __shared__ __align__(16) float As[2][16][36];
    __shared__ __align__(16) float Bs[2][16][132];

    int tid = threadIdx.x;
    int ty = tid >> 4, tx = tid & 15;      // micro: rows ty*2..+1, cols tx*8..+7
    int ar = tid >> 2, ac = (tid & 3) * 4; // A tile: valid for tid<128
    int br = tid >> 5, bc = (tid & 31) * 4;

    unsigned long long acc[2][4];
#pragma unroll
    for (int i = 0; i < 2; i++)
#pragma unroll
        for (int j = 0; j < 4; j++) acc[i][j] = 0ull;

    float4 av, bv0, bv1;
    if (tid < 128) av = *(const float4*)&Ab[(size_t)(m0 + ar) * 512 + ac];
    bv0 = *(const float4*)&Bb[(size_t)br * 128 + bc];
    bv1 = *(const float4*)&Bb[(size_t)(br + 8) * 128 + bc];
    if (tid < 128) {
        As[0][ac + 0][ar] = av.x; As[0][ac + 1][ar] = av.y;
        As[0][ac + 2][ar] = av.z; As[0][ac + 3][ar] = av.w;
    }
    *(float4*)&Bs[0][br][bc] = bv0;
    *(float4*)&Bs[0][br + 8][bc] = bv1;
    __syncthreads();

    int buf = 0;
    for (int c = 0; c < 32; c++) {
        if (c + 1 < 32) {
            int k0 = (c + 1) * 16;
            if (tid < 128) av = *(const float4*)&Ab[(size_t)(m0 + ar) * 512 + k0 + ac];
            bv0 = *(const float4*)&Bb[(size_t)(k0 + br) * 128 + bc];
            bv1 = *(const float4*)&Bb[(size_t)(k0 + br + 8) * 128 + bc];
        }
#pragma unroll
        for (int kk = 0; kk < 16; kk++) {
            float2 a2 = *(const float2*)&As[buf][kk][ty * 2];
            unsigned long long a0 = pack2(a2.x), a1 = pack2(a2.y);
            ulonglong2 b01 = *(const ulonglong2*)&Bs[buf][kk][tx * 8];
            ulonglong2 b23 = *(const ulonglong2*)&Bs[buf][kk][tx * 8 + 4];
            fma2(acc[0][0], a0, b01.x); fma2(acc[0][1], a0, b01.y);
            fma2(acc[0][2], a0, b23.x); fma2(acc[0][3], a0, b23.y);
            fma2(acc[1][0], a1, b01.x); fma2(acc[1][1], a1, b01.y);
            fma2(acc[1][2], a1, b23.x); fma2(acc[1][3], a1, b23.y);
        }
        if (c + 1 < 32) {
            buf ^= 1;
            if (tid < 128) {
                As[buf][ac + 0][ar] = av.x; As[buf][ac + 1][ar] = av.y;
                As[buf][ac + 2][ar] = av.z; As[buf][ac + 3][ar] = av.w;
            }
            *(float4*)&Bs[buf][br][bc] = bv0;
            *(float4*)&Bs[buf][br + 8][bc] = bv1;
            __syncthreads();
        }
    }

#pragma unroll
    for (int r = 0; r < 2; r++) {
        int row = b * 512 + m0 + ty * 2 + r;
        float2 t0 = up2(acc[r][0]), t1 = up2(acc[r][1]),
               t2 = up2(acc[r][2]), t3 = up2(acc[r][3]);
        float4 v0 = make_float4(t0.x, t0.y, t1.x, t1.y);
        float4 v1 = make_float4(t2.x, t2.y, t3.x, t3.y);
        float* dst = &g_Hagg[(size_t)row * 128 + tx * 8];
        *(float4*)dst = v0;
        *(float4*)(dst + 4) = v1;
    }
}

// ---------------------------------------------------------------------------
// Gate GEMM + fused LSTM update:
//   pre = Ges + [H | h_prev] @ Wcomb   (4096 x 512, K=256, interleaved cols)
//   i,f,g,o -> c,h written directly (no G buffer)
// tile 64x128, grid = 64*4 = 256 blocks, 256 threads
// ---------------------------------------------------------------------------
__global__ void __launch_bounds__(256) k_gemmG(int hin, int hout) {
    const float* __restrict__ hprev = g_h[hin];
    float* __restrict__ hnext = g_h[hout];
    int m0 = (blockIdx.x >> 2) * 64;
    int n0 = (blockIdx.x & 3) * 128;

    __shared__ __align__(16) float As[2][16][68];
    __shared__ __align__(16) float Bs[2][16][132];

    int tid = threadIdx.x;
    int ty = tid >> 4, tx = tid & 15;
    int ar = tid >> 2, ac = (tid & 3) * 4;
    int br = tid >> 5, bc = (tid & 31) * 4;

    unsigned long long acc[4][4];
#pragma unroll
    for (int i = 0; i < 4; i++)
#pragma unroll
        for (int j = 0; j < 4; j++) acc[i][j] = 0ull;

    float4 av = *(const float4*)&g_Hagg[(size_t)(m0 + ar) * 128 + ac];
    float4 bv0 = *(const float4*)&g_Wcomb[(size_t)br * 512 + n0 + bc];
    float4 bv1 = *(const float4*)&g_Wcomb[(size_t)(br + 8) * 512 + n0 + bc];
    As[0][ac + 0][ar] = av.x; As[0][ac + 1][ar] = av.y;
    As[0][ac + 2][ar] = av.z; As[0][ac + 3][ar] = av.w;
    *(float4*)&Bs[0][br][bc] = bv0;
    *(float4*)&Bs[0][br + 8][bc] = bv1;
    __syncthreads();

    int buf = 0;
    for (int c = 0; c < 16; c++) {
        if (c + 1 < 16) {
            int k0 = (c + 1) * 16;
            const float* src = (k0 < 128) ? g_Hagg : hprev;
            int kc = k0 & 127;
            av  = *(const float4*)&src[(size_t)(m0 + ar) * 128 + kc + ac];
            bv0 = *(const float4*)&g_Wcomb[(size_t)(k0 + br) * 512 + n0 + bc];
            bv1 = *(const float4*)&g_Wcomb[(size_t)(k0 + br + 8) * 512 + n0 + bc];
        }
#pragma unroll
        for (int kk = 0; kk < 16; kk++) {
            float4 a4 = *(const float4*)&As[buf][kk][ty * 4];
            unsigned long long a0 = pack2(a4.x), a1 = pack2(a4.y),
                               a2 = pack2(a4.z), a3 = pack2(a4.w);
            ulonglong2 b01 = *(const ulonglong2*)&Bs[buf][kk][tx * 8];
            ulonglong2 b23 = *(const ulonglong2*)&Bs[buf][kk][tx * 8 + 4];
            fma2(acc[0][0], a0, b01.x); fma2(acc[0][1], a0, b01.y);
            fma2(acc[0][2], a0, b23.x); fma2(acc[0][3], a0, b23.y);
            fma2(acc[1][0], a1, b01.x); fma2(acc[1][1], a1, b01.y);
            fma2(acc[1][2], a1, b23.x); fma2(acc[1][3], a1, b23.y);
            fma2(acc[2][0], a2, b01.x); fma2(acc[2][1], a2, b01.y);
            fma2(acc[2][2], a2, b23.x); fma2(acc[2][3], a2, b23.y);
            fma2(acc[3][0], a3, b01.x); fma2(acc[3][1], a3, b01.y);
            fma2(acc[3][2], a3, b23.x); fma2(acc[3][3], a3, b23.y);
        }
        if (c + 1 < 16) {
            buf ^= 1;
            As[buf][ac + 0][ar] = av.x; As[buf][ac + 1][ar] = av.y;
            As[buf][ac + 2][ar] = av.z; As[buf][ac + 3][ar] = av.w;
            *(float4*)&Bs[buf][br][bc] = bv0;
            *(float4*)&Bs[buf][br + 8][bc] = bv1;
            __syncthreads();
        }
    }

    // fused gate epilogue: cols n0+tx*8 .. +7 = (j0: i,f,g,o)(j0+1: i,f,g,o)
    int j0 = (n0 + tx * 8) >> 2;
#pragma unroll
    for (int r = 0; r < 4; r++) {
        int rr = m0 + ty * 4 + r;
        float2 t0 = up2(acc[r][0]), t1 = up2(acc[r][1]),
               t2 = up2(acc[r][2]), t3 = up2(acc[r][3]);
        const float* ger = &g_Ges[(size_t)rr * 512 + n0 + tx * 8];
        float4 ge0 = *(const float4*)ger;
        float4 ge1 = *(const float4*)(ger + 4);
        float p0 = t0.x + ge0.x, p1 = t0.y + ge0.y, p2 = t1.x + ge0.z, p3 = t1.y + ge0.w;
        float p4 = t2.x + ge1.x, p5 = t2.y + ge1.y, p6 = t3.x + ge1.z, p7 = t3.y + ge1.w;

        {
            float iv = sigm(p0), fv = sigm(p1), gv = tanhf(p2), ov = sigm(p3);
            int cidx = rr * 128 + j0;
            float cc = fv * g_c[cidx] + iv * gv;
            g_c[cidx] = cc;
            hnext[cidx] = ov * tanhf(cc);
        }
        {
            float iv = sigm(p4), fv = sigm(p5), gv = tanhf(p6), ov = sigm(p7);
            int cidx = rr * 128 + j0 + 1;
            float cc = fv * g_c[cidx] + iv * gv;
            g_c[cidx] = cc;
            hnext[cidx] = ov * tanhf(cc);
        }
    }
}

// ---------------------------------------------------------------------------
// Xi += h_new @ Wout + bout ; write out[:, :, t, :]
// ---------------------------------------------------------------------------
__global__ void __launch_bounds__(256) k_out(int hout, int t, const float* __restrict__ Wout,
                                             const float* __restrict__ bout, float* __restrict__ out) {
    __shared__ float Ws[128 * 64];
    __shared__ float hs[16][128];
    int tid = threadIdx.x;
    int row0 = blockIdx.x * 16;
    const float* __restrict__ h = g_h[hout];

    for (int i = tid; i < 128 * 64; i += 256) Ws[i] = Wout[i];
    for (int i = tid; i < 16 * 128; i += 256)
        hs[i >> 7][i & 127] = h[(size_t)(row0 + (i >> 7)) * 128 + (i & 127)];
    __syncthreads();

#pragma unroll
    for (int kq = 0; kq < 4; kq++) {
        int e  = tid + kq * 256;
        int rr = e >> 6;
        int d  = e & 63;
        int grow = row0 + rr;
        float acc = g_Xi[grow * 64 + d] + bout[d];
#pragma unroll 8
        for (int kk = 0; kk < 128; kk++) acc += hs[rr][kk] * Ws[kk * 64 + d];
        g_Xi[grow * 64 + d] = acc;
        out[(size_t)grow * 4096 + t * 64 + d] = acc;
    }
}

// ---------------------------------------------------------------------------
extern "C" void kernel_launch(void* const* d_in, const int* in_sizes, int n_in,
                              void* d_out, int out_size) {
    const float* X    = (const float*)d_in[0];
    const float* A    = (const float*)d_in[1];
    const float* Wse  = (const float*)d_in[2];
    const float* bse  = (const float*)d_in[3];
    const float* Wpe  = (const float*)d_in[4];
    const float* bpe  = (const float*)d_in[5];
    const float* Wii  = (const float*)d_in[6];
    const float* bii  = (const float*)d_in[7];
    const float* Whi  = (const float*)d_in[8];
    const float* bhi  = (const float*)d_in[9];
    const float* Wif  = (const float*)d_in[10];
    const float* bif_ = (const float*)d_in[11];
    const float* Whf  = (const float*)d_in[12];
    const float* bhf  = (const float*)d_in[13];
    const float* Wig  = (const float*)d_in[14];
    const float* big_ = (const float*)d_in[15];
    const float* Whg  = (const float*)d_in[16];
    const float* bhg  = (const float*)d_in[17];
    const float* Wio  = (const float*)d_in[18];
    const float* bio  = (const float*)d_in[19];
    const float* Who  = (const float*)d_in[20];
    const float* bho  = (const float*)d_in[21];
    const float* Wout = (const float*)d_in[22];
    const float* bout = (const float*)d_in[23];
    float* out = (float*)d_out;

    k_dinv<<<Rc, 128>>>(A);
    k_an<<<2048, 256>>>(A);
    k_prep<<<512, 128>>>(Wii, bii, Whi, bhi, Wif, bif_, Whf, bhf,
                         Wig, big_, Whg, bhg, Wio, bio, Who, bho, Wpe, bpe);
    k_init<<<Rc, 128>>>(X, Wse, bse, out);
    k_ges<<<256, 256>>>();

    for (int t = 1; t < Tc; t++) {
        int hin  = (t - 1) & 1;
        int hout = t & 1;
        k_gemmH<<<128, 256>>>(hin);
        k_gemmG<<<256, 256>>>(hin, hout);
        k_out<<<256, 256>>>(hout, t, Wout, bout, out);
    }
}

// round 4
// speedup vs baseline: 1.8203x; 1.8203x over previous
#include <cuda_runtime.h>
#include <cuda_bf16.h>
#include <math.h>
#include <stdint.h>

// Problem constants
#define Bc   8
#define Nc   512
#define Tc   64
#define NINc 64
#define NHc  128
#define Rc   (Bc * Nc)   // 4096 rows

// ---------------- scratch (device globals) ----------------------------------
__device__ float g_dinv[Rc];
__device__ __nv_bfloat16 g_Anh[Bc * Nc * Nc];   // An hi (4 MB)
__device__ __nv_bfloat16 g_Anl[Bc * Nc * Nc];   // An lo
__device__ float g_es[Rc * NHc];                // static embedding fp32
__device__ float g_Wes[128 * 512];              // Wi[0:128] interleaved fp32
__device__ float g_bbig[512];
__device__ float g_Ges[Rc * 512];               // es @ Wes + bbig (fp32, interleaved)
__device__ __nv_bfloat16 g_WTh[512 * 256];      // Wcomb^T hi: [n][k]
__device__ __nv_bfloat16 g_WTl[512 * 256];
__device__ __nv_bfloat16 g_Hh[Rc * NHc];        // H = An@h, hi/lo, row-major
__device__ __nv_bfloat16 g_Hl[Rc * NHc];
__device__ __nv_bfloat16 g_hrh[2][Rc * NHc];    // h row-major hi/lo (double buffered)
__device__ __nv_bfloat16 g_hrl[2][Rc * NHc];
__device__ __nv_bfloat16 g_hTh[2][Bc * NHc * Nc]; // h transposed per batch [b][j][n]
__device__ __nv_bfloat16 g_hTl[2][Bc * NHc * Nc];
__device__ float g_hf[Rc * NHc];                // h fp32 (for k_out)
__device__ float g_c[Rc * NHc];                 // cell state
__device__ float g_Xi[Rc * NINc];               // running output accumulator

// ---------------- helpers ----------------------------------------------------
__device__ __forceinline__ uint32_t smem_u32(const void* p) {
    uint32_t a;
    asm("{ .reg .u64 t; cvta.to.shared.u64 t, %1; cvt.u32.u64 %0, t; }" : "=r"(a) : "l"(p));
    return a;
}
__device__ __forceinline__ float sigm(float x) { return 1.f / (1.f + expf(-x)); }
__device__ __forceinline__ void bsplit(float v, __nv_bfloat16& hi, __nv_bfloat16& lo) {
    hi = __float2bfloat16(v);
    lo = __float2bfloat16(v - __bfloat162float(hi));
}

__device__ __forceinline__ void cpa16(uint32_t dst, const void* src) {
    asm volatile("cp.async.cg.shared.global [%0], [%1], 16;" :: "r"(dst), "l"(src) : "memory");
}
#define CP_COMMIT() asm volatile("cp.async.commit_group;" ::: "memory")
#define CP_WAIT1()  asm volatile("cp.async.wait_group 1;" ::: "memory")

__device__ __forceinline__ void ldsm4(uint32_t* r, uint32_t a) {
    asm volatile("ldmatrix.sync.aligned.m8n8.x4.shared.b16 {%0,%1,%2,%3}, [%4];"
        : "=r"(r[0]), "=r"(r[1]), "=r"(r[2]), "=r"(r[3]) : "r"(a));
}
__device__ __forceinline__ void mmabf(float* d, const uint32_t* a, const uint32_t* b) {
    asm volatile("mma.sync.aligned.m16n8k16.row.col.f32.bf16.bf16.f32 "
        "{%0,%1,%2,%3}, {%4,%5,%6,%7}, {%8,%9}, {%0,%1,%2,%3};"
        : "+f"(d[0]), "+f"(d[1]), "+f"(d[2]), "+f"(d[3])
        : "r"(a[0]), "r"(a[1]), "r"(a[2]), "r"(a[3]), "r"(b[0]), "r"(b[1]));
}

// smem tile row stride: 72 bf16 = 144 B (16B-aligned, conflict-free for ldmatrix)
#define RS 144

// ---------------------------------------------------------------------------
__global__ void k_dinv(const float* __restrict__ A) {
    int row = blockIdx.x;
    const float* arow = A + (size_t)row * Nc;
    float s = 0.f;
    for (int j = threadIdx.x; j < Nc; j += blockDim.x) s += arow[j];
    __shared__ float sh[128];
    sh[threadIdx.x] = s;
    __syncthreads();
    for (int off = 64; off > 0; off >>= 1) {
        if (threadIdx.x < off) sh[threadIdx.x] += sh[threadIdx.x + off];
        __syncthreads();
    }
    if (threadIdx.x == 0) {
        float d = sh[0];
        g_dinv[row] = (d > 0.f) ? rsqrtf(d) : 0.f;
    }
}

// An = A * dinv_i * dinv_j -> bf16 hi/lo
__global__ void k_an(const float* __restrict__ A) {
    int idx = blockIdx.x * blockDim.x + threadIdx.x;
    int e = idx * 4;
    int b   = e >> 18;
    int rem = e & 262143;
    int i   = rem >> 9;
    int j   = rem & 511;
    float4 a = *(const float4*)(A + (size_t)e);
    float di = g_dinv[b * 512 + i];
    const float* dj = g_dinv + b * 512 + j;
    float v[4] = { a.x * di * dj[0], a.y * di * dj[1], a.z * di * dj[2], a.w * di * dj[3] };
    __nv_bfloat16 h[4], l[4];
#pragma unroll
    for (int q = 0; q < 4; q++) bsplit(v[q], h[q], l[q]);
    __nv_bfloat162* ph = (__nv_bfloat162*)(g_Anh + (size_t)e);
    __nv_bfloat162* pl = (__nv_bfloat162*)(g_Anl + (size_t)e);
    ph[0] = __nv_bfloat162(h[0], h[1]); ph[1] = __nv_bfloat162(h[2], h[3]);
    pl[0] = __nv_bfloat162(l[0], l[1]); pl[1] = __nv_bfloat162(l[2], l[3]);
}

// ---------------------------------------------------------------------------
// Build Wes (fp32, interleaved n=j*4+g), WcombT hi/lo (bf16 [n][k]), bbig
// ---------------------------------------------------------------------------
__global__ void k_prep(const float* __restrict__ Wii, const float* __restrict__ bii,
                       const float* __restrict__ Whi, const float* __restrict__ bhi,
                       const float* __restrict__ Wif, const float* __restrict__ bif_,
                       const float* __restrict__ Whf, const float* __restrict__ bhf,
                       const float* __restrict__ Wig, const float* __restrict__ big_,
                       const float* __restrict__ Whg, const float* __restrict__ bhg,
                       const float* __restrict__ Wio, const float* __restrict__ bio,
                       const float* __restrict__ Who, const float* __restrict__ bho,
                       const float* __restrict__ Wpe, const float* __restrict__ bpe) {
    int n = blockIdx.x;
    int g = n & 3;
    int j = n >> 2;
    int t = threadIdx.x;
    const float* Wi = (g == 0) ? Wii : (g == 1) ? Wif : (g == 2) ? Wig : Wio;
    const float* Wh = (g == 0) ? Whi : (g == 1) ? Whf : (g == 2) ? Whg : Who;
    const float* bi = (g == 0) ? bii : (g == 1) ? bif_ : (g == 2) ? big_ : bio;
    const float* bh = (g == 0) ? bhi : (g == 1) ? bhf : (g == 2) ? bhg : bho;

    __shared__ float wcol[128];
    wcol[t] = Wi[(128 + t) * 128 + j];
    __syncthreads();

    g_Wes[t * 512 + n] = Wi[t * 128 + j];

    float acc = 0.f;
    const float* wpet = Wpe + t * 128;
#pragma unroll 8
    for (int m = 0; m < 128; m++) acc += wpet[m] * wcol[m];

    __nv_bfloat16 hh, ll;
    bsplit(acc, hh, ll);
    g_WTh[n * 256 + t] = hh;
    g_WTl[n * 256 + t] = ll;
    float whv = Wh[t * 128 + j];
    bsplit(whv, hh, ll);
    g_WTh[n * 256 + 128 + t] = hh;
    g_WTl[n * 256 + 128 + t] = ll;

    if (t == 0) {
        float ba = bi[j] + bh[j];
        for (int m = 0; m < 128; m++) ba += bpe[m] * wcol[m];
        g_bbig[n] = ba;
    }
}

// ---------------------------------------------------------------------------
// Init: es = X0@Wse + bse ; zero h layouts & c ; Xi = X0 ; out t=0
// ---------------------------------------------------------------------------
__global__ void k_init(const float* __restrict__ X, const float* __restrict__ Wse,
                       const float* __restrict__ bse, float* __restrict__ out) {
    int row = blockIdx.x;
    int t = threadIdx.x;
    __shared__ float x0[64];
    if (t < 64) {
        float v = X[(size_t)row * 4096 + t];
        x0[t] = v;
        g_Xi[row * 64 + t] = v;
        out[(size_t)row * 4096 + t] = v;
    }
    __syncthreads();
    float acc = bse[t];
#pragma unroll 8
    for (int k = 0; k < 64; k++) acc += x0[k] * Wse[k * 128 + t];
    g_es[row * 128 + t] = acc;

    __nv_bfloat16 z = __float2bfloat16(0.f);
    g_hrh[0][(size_t)row * 128 + t] = z;
    g_hrl[0][(size_t)row * 128 + t] = z;
    int bb = row >> 9, nn = row & 511;
    g_hTh[0][(size_t)(bb * 128 + t) * 512 + nn] = z;
    g_hTl[0][(size_t)(bb * 128 + t) * 512 + nn] = z;
    g_c[row * 128 + t] = 0.f;
}

// ---------------------------------------------------------------------------
// k_ges: Ges = es @ Wes + bbig (4096 x 512, K=128) fp32, runs once
// ---------------------------------------------------------------------------
__global__ void __launch_bounds__(256) k_ges() {
    int m0 = (blockIdx.x >> 2) * 64;
    int n0 = (blockIdx.x & 3) * 128;

    __shared__ __align__(16) float As[16][68];
    __shared__ __align__(16) float Bs[16][132];

    int tid = threadIdx.x;
    int ty = tid >> 4, tx = tid & 15;
    int ar = tid >> 2, ac = (tid & 3) * 4;
    int br = tid >> 5, bc = (tid & 31) * 4;

    float acc[4][8] = {};

    for (int k0 = 0; k0 < 128; k0 += 16) {
        float4 av = *(const float4*)&g_es[(size_t)(m0 + ar) * 128 + k0 + ac];
        float4 bv0 = *(const float4*)&g_Wes[(size_t)(k0 + br) * 512 + n0 + bc];
        float4 bv1 = *(const float4*)&g_Wes[(size_t)(k0 + br + 8) * 512 + n0 + bc];
        As[ac + 0][ar] = av.x; As[ac + 1][ar] = av.y;
        As[ac + 2][ar] = av.z; As[ac + 3][ar] = av.w;
        *(float4*)&Bs[br][bc] = bv0;
        *(float4*)&Bs[br + 8][bc] = bv1;
        __syncthreads();
#pragma unroll
        for (int kk = 0; kk < 16; kk++) {
            float4 a4 = *(const float4*)&As[kk][ty * 4];
            float4 b0 = *(const float4*)&Bs[kk][tx * 8];
            float4 b1 = *(const float4*)&Bs[kk][tx * 8 + 4];
            float av4[4] = { a4.x, a4.y, a4.z, a4.w };
            float bv8[8] = { b0.x, b0.y, b0.z, b0.w, b1.x, b1.y, b1.z, b1.w };
#pragma unroll
            for (int i = 0; i < 4; i++)
#pragma unroll
                for (int jq = 0; jq < 8; jq++) acc[i][jq] += av4[i] * bv8[jq];
        }
        __syncthreads();
    }

    float bb[8];
#pragma unroll
    for (int q = 0; q < 8; q++) bb[q] = g_bbig[n0 + tx * 8 + q];
#pragma unroll
    for (int r = 0; r < 4; r++) {
        int rr = m0 + ty * 4 + r;
        float* dst = &g_Ges[(size_t)rr * 512 + n0 + tx * 8];
#pragma unroll
        for (int q = 0; q < 8; q++) dst[q] = acc[r][q] + bb[q];
    }
}

// ---------------------------------------------------------------------------
// k_gH: H = An @ h (per batch 512x512 @ 512x128), bf16 3-product via mma.sync
// grid = 8 batches * 8 mtiles(64) = 64 CTAs, 256 thr (8 warps, 2m x 4n, 32x32)
// smem: stage = A(64x72) + B(128x72) bf16 = 27648 B, double buffered (55296)
// ---------------------------------------------------------------------------
#define H_AB   (64 * RS)          // 9216
#define H_STG  (H_AB + 128 * RS)  // 27648
#define H_NC   24
__global__ void __launch_bounds__(256) k_gH(int hin) {
    extern __shared__ __align__(16) char dsm[];
    uint32_t sbase = smem_u32(dsm);
    int tid = threadIdx.x, wid = tid >> 5, lane = tid & 31;
    int wm = wid >> 2, wn = wid & 3;
    int b  = blockIdx.x >> 3;
    int m0 = (blockIdx.x & 7) * 64;

    float acc[2][4][4];
#pragma unroll
    for (int i = 0; i < 2; i++)
#pragma unroll
        for (int j = 0; j < 4; j++)
#pragma unroll
            for (int q = 0; q < 4; q++) acc[i][j][q] = 0.f;

    // per-chunk cp.async issue
    auto issue = [&](int cc, uint32_t bufA, uint32_t bufB) {
        int ph = cc >> 3, kc = (cc & 7) * 64;
        const __nv_bfloat16* As = ((ph == 1) ? g_Anl : g_Anh)
            + (size_t)b * 262144 + (size_t)m0 * 512 + kc;
        const __nv_bfloat16* Bs = ((ph == 2) ? g_hTl[hin] : g_hTh[hin])
            + (size_t)b * 65536 + kc;
#pragma unroll
        for (int i = 0; i < 2; i++) {
            int idx = tid + i * 256, r = idx >> 3, c = idx & 7;
            cpa16(bufA + r * RS + c * 16, As + (size_t)r * 512 + c * 8);
        }
#pragma unroll
        for (int i = 0; i < 4; i++) {
            int idx = tid + i * 256, r = idx >> 3, c = idx & 7;
            cpa16(bufB + r * RS + c * 16, Bs + (size_t)r * 512 + c * 8);
        }
    };

    issue(0, sbase, sbase + H_AB);
    CP_COMMIT();

#pragma unroll 1
    for (int cc = 0; cc < H_NC; cc++) {
        int sn = (cc + 1) & 1;
        if (cc + 1 < H_NC)
            issue(cc + 1, sbase + sn * H_STG, sbase + sn * H_STG + H_AB);
        CP_COMMIT();
        CP_WAIT1();
        __syncthreads();

        int s = cc & 1;
        uint32_t bufA = sbase + s * H_STG;
        uint32_t bufB = bufA + H_AB;
        uint32_t aBase = bufA + (uint32_t)(wm * 32 + (lane & 15)) * RS + ((lane >> 4) * 16);
        uint32_t bBase = bufB + (uint32_t)(wn * 32 + (lane & 7) + ((lane >> 4) & 1) * 8) * RS
                              + (((lane >> 3) & 1) * 16);
#pragma unroll
        for (int ks = 0; ks < 4; ks++) {
            uint32_t a[2][4], b0[4], b1[4];
            ldsm4(a[0], aBase + ks * 32);
            ldsm4(a[1], aBase + 16 * RS + ks * 32);
            ldsm4(b0, bBase + ks * 32);
            ldsm4(b1, bBase + 16 * RS + ks * 32);
#pragma unroll
            for (int mf = 0; mf < 2; mf++) {
                mmabf(acc[mf][0], a[mf], &b0[0]);
                mmabf(acc[mf][1], a[mf], &b0[2]);
                mmabf(acc[mf][2], a[mf], &b1[0]);
                mmabf(acc[mf][3], a[mf], &b1[2]);
            }
        }
        __syncthreads();
    }

    // epilogue: write H hi/lo row-major straight from fragments
    int rbase = b * 512 + m0 + wm * 32 + (lane >> 2);
    int cbase = wn * 32 + (lane & 3) * 2;
#pragma unroll
    for (int mf = 0; mf < 2; mf++) {
#pragma unroll
        for (int nf = 0; nf < 4; nf++) {
            int col = cbase + nf * 8;
            float* d = acc[mf][nf];
            __nv_bfloat16 h0, l0, h1, l1;
            int r0 = rbase + mf * 16;
            bsplit(d[0], h0, l0); bsplit(d[1], h1, l1);
            *(__nv_bfloat162*)(g_Hh + (size_t)r0 * 128 + col) = __nv_bfloat162(h0, h1);
            *(__nv_bfloat162*)(g_Hl + (size_t)r0 * 128 + col) = __nv_bfloat162(l0, l1);
            bsplit(d[2], h0, l0); bsplit(d[3], h1, l1);
            *(__nv_bfloat162*)(g_Hh + (size_t)(r0 + 8) * 128 + col) = __nv_bfloat162(h0, h1);
            *(__nv_bfloat162*)(g_Hl + (size_t)(r0 + 8) * 128 + col) = __nv_bfloat162(l0, l1);
        }
    }
}

// ---------------------------------------------------------------------------
// k_gG: gates = Ges + [H | h] @ Wcomb (4096x512, K=256), bf16 3-product,
// fused LSTM epilogue. grid = 32 mtiles(128) * 4 ntiles(128) = 128 CTAs,
// 256 thr (8 warps, 2m x 4n, warp tile 64x32).
// smem: stage = A(128x72)+B(128x72) = 36864 B, double buffered (73728);
// epilogue reuses dsm as fp32 stage 128x132 (67584 B).
// ---------------------------------------------------------------------------
#define G_AB   (128 * RS)          // 18432
#define G_STG  (G_AB + 128 * RS)   // 36864
#define G_NC   12
__global__ void __launch_bounds__(256) k_gG(int hin, int hout) {
    extern __shared__ __align__(16) char dsm[];
    uint32_t sbase = smem_u32(dsm);
    int tid = threadIdx.x, wid = tid >> 5, lane = tid & 31;
    int wm = wid >> 2, wn = wid & 3;
    int m0 = (blockIdx.x >> 2) * 128;
    int n0 = (blockIdx.x & 3) * 128;

    float acc[4][4][4];
#pragma unroll
    for (int i = 0; i < 4; i++)
#pragma unroll
        for (int j = 0; j < 4; j++)
#pragma unroll
            for (int q = 0; q < 4; q++) acc[i][j][q] = 0.f;

    auto issue = [&](int cc, uint32_t bufA, uint32_t bufB) {
        int ph = cc >> 2, kk = (cc & 3) * 64;
        const __nv_bfloat16* As;
        if (kk < 128)
            As = ((ph == 1) ? g_Hl : g_Hh) + (size_t)m0 * 128 + kk;
        else
            As = ((ph == 1) ? g_hrl[hin] : g_hrh[hin]) + (size_t)m0 * 128 + (kk - 128);
        const __nv_bfloat16* Bs = ((ph == 2) ? g_WTl : g_WTh) + (size_t)n0 * 256 + kk;
#pragma unroll
        for (int i = 0; i < 4; i++) {
            int idx = tid + i * 256, r = idx >> 3, c = idx & 7;
            cpa16(bufA + r * RS + c * 16, As + (size_t)r * 128 + c * 8);
        }
#pragma unroll
        for (int i = 0; i < 4; i++) {
            int idx = tid + i * 256, r = idx >> 3, c = idx & 7;
            cpa16(bufB + r * RS + c * 16, Bs + (size_t)r * 256 + c * 8);
        }
    };

    issue(0, sbase, sbase + G_AB);
    CP_COMMIT();

#pragma unroll 1
    for (int cc = 0; cc < G_NC; cc++) {
        int sn = (cc + 1) & 1;
        if (cc + 1 < G_NC)
            issue(cc + 1, sbase + sn * G_STG, sbase + sn * G_STG + G_AB);
        CP_COMMIT();
        CP_WAIT1();
        __syncthreads();

        int s = cc & 1;
        uint32_t bufA = sbase + s * G_STG;
        uint32_t bufB = bufA + G_AB;
        uint32_t aBase = bufA + (uint32_t)(wm * 64 + (lane & 15)) * RS + ((lane >> 4) * 16);
        uint32_t bBase = bufB + (uint32_t)(wn * 32 + (lane & 7) + ((lane >> 4) & 1) * 8) * RS
                              + (((lane >> 3) & 1) * 16);
#pragma unroll
        for (int ks = 0; ks < 4; ks++) {
            uint32_t a[4][4], b0[4], b1[4];
            ldsm4(a[0], aBase + ks * 32);
            ldsm4(a[1], aBase + 16 * RS + ks * 32);
            ldsm4(a[2], aBase + 32 * RS + ks * 32);
            ldsm4(a[3], aBase + 48 * RS + ks * 32);
            ldsm4(b0, bBase + ks * 32);
            ldsm4(b1, bBase + 16 * RS + ks * 32);
#pragma unroll
            for (int mf = 0; mf < 4; mf++) {
                mmabf(acc[mf][0], a[mf], &b0[0]);
                mmabf(acc[mf][1], a[mf], &b0[2]);
                mmabf(acc[mf][2], a[mf], &b1[0]);
                mmabf(acc[mf][3], a[mf], &b1[2]);
            }
        }
        __syncthreads();
    }

    // stage fp32 tile in smem (reuse dsm), then fused gate epilogue
    float* cst = (float*)dsm;   // [128][132]
#pragma unroll
    for (int mf = 0; mf < 4; mf++) {
#pragma unroll
        for (int nf = 0; nf < 4; nf++) {
            int row = wm * 64 + mf * 16 + (lane >> 2);
            int col = wn * 32 + nf * 8 + (lane & 3) * 2;
            float* d = acc[mf][nf];
            *(float2*)&cst[row * 132 + col]       = make_float2(d[0], d[1]);
            *(float2*)&cst[(row + 8) * 132 + col] = make_float2(d[2], d[3]);
        }
    }
    __syncthreads();

    __nv_bfloat16* hTh = g_hTh[hout];
    __nv_bfloat16* hTl = g_hTl[hout];
    __nv_bfloat16* hrho = g_hrh[hout];
    __nv_bfloat16* hrlo = g_hrl[hout];
#pragma unroll
    for (int i = 0; i < 16; i++) {
        int idx = tid + i * 256;
        int r = idx >> 5, q = idx & 31;       // row within tile, feature quad
        int rr = m0 + r;
        int j = (n0 >> 2) + q;                // global feature index
        float4 pv = *(float4*)&cst[r * 132 + q * 4];
        float4 ge = *(const float4*)&g_Ges[(size_t)rr * 512 + j * 4];
        float pi = pv.x + ge.x, pf = pv.y + ge.y, pg = pv.z + ge.z, po = pv.w + ge.w;
        float iv = sigm(pi), fv = sigm(pf), gv = tanhf(pg), ov = sigm(po);
        size_t cidx = (size_t)rr * 128 + j;
        float cc = fv * g_c[cidx] + iv * gv;
        g_c[cidx] = cc;
        float hv = ov * tanhf(cc);
        g_hf[cidx] = hv;
        __nv_bfloat16 hh, ll;
        bsplit(hv, hh, ll);
        hrho[cidx] = hh;
        hrlo[cidx] = ll;
        int bb = rr >> 9, nn = rr & 511;
        size_t tidx = (size_t)(bb * 128 + j) * 512 + nn;
        hTh[tidx] = hh;
        hTl[tidx] = ll;
    }
}

// ---------------------------------------------------------------------------
// Xi += h_new @ Wout + bout ; write out[:, :, t, :]
// ---------------------------------------------------------------------------
__global__ void __launch_bounds__(256) k_out(int t, const float* __restrict__ Wout,
                                             const float* __restrict__ bout, float* __restrict__ out) {
    __shared__ float Ws[128 * 64];
    __shared__ float hs[16][128];
    int tid = threadIdx.x;
    int row0 = blockIdx.x * 16;

    for (int i = tid; i < 128 * 64; i += 256) Ws[i] = Wout[i];
    for (int i = tid; i < 16 * 128; i += 256)
        hs[i >> 7][i & 127] = g_hf[(size_t)(row0 + (i >> 7)) * 128 + (i & 127)];
    __syncthreads();

#pragma unroll
    for (int kq = 0; kq < 4; kq++) {
        int e  = tid + kq * 256;
        int rr = e >> 6;
        int d  = e & 63;
        int grow = row0 + rr;
        float acc = g_Xi[grow * 64 + d] + bout[d];
#pragma unroll 8
        for (int kk = 0; kk < 128; kk++) acc += hs[rr][kk] * Ws[kk * 64 + d];
        g_Xi[grow * 64 + d] = acc;
        out[(size_t)grow * 4096 + t * 64 + d] = acc;
    }
}

// ---------------------------------------------------------------------------
extern "C" void kernel_launch(void* const* d_in, const int* in_sizes, int n_in,
                              void* d_out, int out_size) {
    const float* X    = (const float*)d_in[0];
    const float* A    = (const float*)d_in[1];
    const float* Wse  = (const float*)d_in[2];
    const float* bse  = (const float*)d_in[3];
    const float* Wpe  = (const float*)d_in[4];
    const float* bpe  = (const float*)d_in[5];
    const float* Wii  = (const float*)d_in[6];
    const float* bii  = (const float*)d_in[7];
    const float* Whi  = (const float*)d_in[8];
    const float* bhi  = (const float*)d_in[9];
    const float* Wif  = (const float*)d_in[10];
    const float* bif_ = (const float*)d_in[11];
    const float* Whf  = (const float*)d_in[12];
    const float* bhf  = (const float*)d_in[13];
    const float* Wig  = (const float*)d_in[14];
    const float* big_ = (const float*)d_in[15];
    const float* Whg  = (const float*)d_in[16];
    const float* bhg  = (const float*)d_in[17];
    const float* Wio  = (const float*)d_in[18];
    const float* bio  = (const float*)d_in[19];
    const float* Who  = (const float*)d_in[20];
    const float* bho  = (const float*)d_in[21];
    const float* Wout = (const float*)d_in[22];
    const float* bout = (const float*)d_in[23];
    float* out = (float*)d_out;

    cudaFuncSetAttribute(k_gH, cudaFuncAttributeMaxDynamicSharedMemorySize, 2 * H_STG);
    cudaFuncSetAttribute(k_gG, cudaFuncAttributeMaxDynamicSharedMemorySize, 2 * G_STG);

    k_dinv<<<Rc, 128>>>(A);
    k_an<<<2048, 256>>>(A);
    k_prep<<<512, 128>>>(Wii, bii, Whi, bhi, Wif, bif_, Whf, bhf,
                         Wig, big_, Whg, bhg, Wio, bio, Who, bho, Wpe, bpe);
    k_init<<<Rc, 128>>>(X, Wse, bse, out);
    k_ges<<<256, 256>>>();

    for (int t = 1; t < Tc; t++) {
        int hin  = (t - 1) & 1;
        int hout = t & 1;
        k_gH<<<64, 256, 2 * H_STG>>>(hin);
        k_gG<<<128, 256, 2 * G_STG>>>(hin, hout);
        k_out<<<256, 256>>>(t, Wout, bout, out);
    }
}

// round 5
// speedup vs baseline: 2.0741x; 1.1395x over previous
#include <cuda_runtime.h>
#include <cuda_bf16.h>
#include <math.h>
#include <stdint.h>

// Problem constants
#define Bc   8
#define Nc   512
#define Tc   64
#define NINc 64
#define NHc  128
#define Rc   (Bc * Nc)   // 4096 rows
#define NCTA 128

// ---------------- scratch (device globals) ----------------------------------
__device__ float g_dinv[Rc];
__device__ __nv_bfloat16 g_Anh[Bc * Nc * Nc];   // An hi (4 MB)
__device__ __nv_bfloat16 g_Anl[Bc * Nc * Nc];   // An lo
__device__ float g_es[Rc * NHc];                // static embedding fp32
__device__ float g_Wes[128 * 512];              // Wi[0:128] interleaved fp32
__device__ float g_bbig[512];
__device__ float g_Ges[Rc * 512];               // es @ Wes + bbig (fp32, interleaved)
__device__ __nv_bfloat16 g_WTh[512 * 256];      // Wcomb^T hi: [n][k]
__device__ __nv_bfloat16 g_WTl[512 * 256];
__device__ __nv_bfloat16 g_Hh[Rc * NHc];        // H = An@h, hi/lo, row-major
__device__ __nv_bfloat16 g_Hl[Rc * NHc];
__device__ __nv_bfloat16 g_hrh[2][Rc * NHc];    // h row-major hi/lo (double buffered)
__device__ __nv_bfloat16 g_hrl[2][Rc * NHc];
__device__ __nv_bfloat16 g_hTh[2][Bc * NHc * Nc]; // h transposed per batch [b][j][n]
__device__ __nv_bfloat16 g_hTl[2][Bc * NHc * Nc];
__device__ float g_hf[Rc * NHc];                // h fp32 (for out phase)
__device__ float g_c[Rc * NHc];                 // cell state
__device__ float g_Xi[Rc * NINc];               // running output accumulator
__device__ unsigned g_count;                    // grid barrier arrive counter
__device__ unsigned g_sense;                    // grid barrier generation

// ---------------- helpers ----------------------------------------------------
__device__ __forceinline__ uint32_t smem_u32(const void* p) {
    uint32_t a;
    asm("{ .reg .u64 t; cvta.to.shared.u64 t, %1; cvt.u32.u64 %0, t; }" : "=r"(a) : "l"(p));
    return a;
}
__device__ __forceinline__ float sigm(float x) { return 1.f / (1.f + expf(-x)); }
__device__ __forceinline__ void bsplit(float v, __nv_bfloat16& hi, __nv_bfloat16& lo) {
    hi = __float2bfloat16(v);
    lo = __float2bfloat16(v - __bfloat162float(hi));
}
__device__ __forceinline__ void cpa16(uint32_t dst, const void* src) {
    asm volatile("cp.async.cg.shared.global [%0], [%1], 16;" :: "r"(dst), "l"(src) : "memory");
}
#define CP_COMMIT() asm volatile("cp.async.commit_group;" ::: "memory")
#define CP_WAIT1()  asm volatile("cp.async.wait_group 1;" ::: "memory")
#define CP_WAIT0()  asm volatile("cp.async.wait_group 0;" ::: "memory")

__device__ __forceinline__ void ldsm4(uint32_t* r, uint32_t a) {
    asm volatile("ldmatrix.sync.aligned.m8n8.x4.shared.b16 {%0,%1,%2,%3}, [%4];"
        : "=r"(r[0]), "=r"(r[1]), "=r"(r[2]), "=r"(r[3]) : "r"(a));
}
__device__ __forceinline__ void mmabf(float* d, const uint32_t* a, const uint32_t* b) {
    asm volatile("mma.sync.aligned.m16n8k16.row.col.f32.bf16.bf16.f32 "
        "{%0,%1,%2,%3}, {%4,%5,%6,%7}, {%8,%9}, {%0,%1,%2,%3};"
        : "+f"(d[0]), "+f"(d[1]), "+f"(d[2]), "+f"(d[3])
        : "r"(a[0]), "r"(a[1]), "r"(a[2]), "r"(a[3]), "r"(b[0]), "r"(b[1]));
}

// grid-wide sense barrier (all 128 CTAs co-resident by construction)
__device__ __forceinline__ void gbar(unsigned gen) {
    __syncthreads();
    if (threadIdx.x == 0) {
        unsigned prev;
        asm volatile("atom.release.gpu.add.u32 %0, [%1], %2;"
                     : "=r"(prev) : "l"(&g_count), "r"(1u) : "memory");
        if (prev == NCTA - 1) {
            g_count = 0u;
            asm volatile("st.release.gpu.u32 [%0], %1;" :: "l"(&g_sense), "r"(gen) : "memory");
        } else {
            unsigned s;
            do {
                asm volatile("ld.acquire.gpu.u32 %0, [%1];" : "=r"(s) : "l"(&g_sense) : "memory");
            } while (s < gen);
        }
    }
    __syncthreads();
}

#define RS 144        // smem row stride bytes (72 bf16)

// smem layout for k_main (dynamic):
//   [0, 73728)            GEMM stages (gG: 2 x 36864; gH: 2 x 18432; gG epi: 67584)
//   [73728, 106496)       Ws: Wout 128x64 fp32 (persistent, loaded once)
//   [106496, 122880)      hs: 32x128 fp32 (out phase)
#define SM_WS   73728
#define SM_HS   106496
#define SM_MAIN 122880

// ---------------------------------------------------------------------------
__global__ void k_dinv(const float* __restrict__ A) {
    int row = blockIdx.x;
    const float* arow = A + (size_t)row * Nc;
    float s = 0.f;
    for (int j = threadIdx.x; j < Nc; j += blockDim.x) s += arow[j];
    __shared__ float sh[128];
    sh[threadIdx.x] = s;
    __syncthreads();
    for (int off = 64; off > 0; off >>= 1) {
        if (threadIdx.x < off) sh[threadIdx.x] += sh[threadIdx.x + off];
        __syncthreads();
    }
    if (threadIdx.x == 0) {
        float d = sh[0];
        g_dinv[row] = (d > 0.f) ? rsqrtf(d) : 0.f;
    }
}

__global__ void k_an(const float* __restrict__ A) {
    int idx = blockIdx.x * blockDim.x + threadIdx.x;
    int e = idx * 4;
    int b   = e >> 18;
    int rem = e & 262143;
    int i   = rem >> 9;
    int j   = rem & 511;
    float4 a = *(const float4*)(A + (size_t)e);
    float di = g_dinv[b * 512 + i];
    const float* dj = g_dinv + b * 512 + j;
    float v[4] = { a.x * di * dj[0], a.y * di * dj[1], a.z * di * dj[2], a.w * di * dj[3] };
    __nv_bfloat16 h[4], l[4];
#pragma unroll
    for (int q = 0; q < 4; q++) bsplit(v[q], h[q], l[q]);
    __nv_bfloat162* ph = (__nv_bfloat162*)(g_Anh + (size_t)e);
    __nv_bfloat162* pl = (__nv_bfloat162*)(g_Anl + (size_t)e);
    ph[0] = __nv_bfloat162(h[0], h[1]); ph[1] = __nv_bfloat162(h[2], h[3]);
    pl[0] = __nv_bfloat162(l[0], l[1]); pl[1] = __nv_bfloat162(l[2], l[3]);
}

// ---------------------------------------------------------------------------
__global__ void k_prep(const float* __restrict__ Wii, const float* __restrict__ bii,
                       const float* __restrict__ Whi, const float* __restrict__ bhi,
                       const float* __restrict__ Wif, const float* __restrict__ bif_,
                       const float* __restrict__ Whf, const float* __restrict__ bhf,
                       const float* __restrict__ Wig, const float* __restrict__ big_,
                       const float* __restrict__ Whg, const float* __restrict__ bhg,
                       const float* __restrict__ Wio, const float* __restrict__ bio,
                       const float* __restrict__ Who, const float* __restrict__ bho,
                       const float* __restrict__ Wpe, const float* __restrict__ bpe) {
    int n = blockIdx.x;
    int g = n & 3;
    int j = n >> 2;
    int t = threadIdx.x;
    const float* Wi = (g == 0) ? Wii : (g == 1) ? Wif : (g == 2) ? Wig : Wio;
    const float* Wh = (g == 0) ? Whi : (g == 1) ? Whf : (g == 2) ? Whg : Who;
    const float* bi = (g == 0) ? bii : (g == 1) ? bif_ : (g == 2) ? big_ : bio;
    const float* bh = (g == 0) ? bhi : (g == 1) ? bhf : (g == 2) ? bhg : bho;

    __shared__ float wcol[128];
    wcol[t] = Wi[(128 + t) * 128 + j];
    __syncthreads();

    g_Wes[t * 512 + n] = Wi[t * 128 + j];

    float acc = 0.f;
    const float* wpet = Wpe + t * 128;
#pragma unroll 8
    for (int m = 0; m < 128; m++) acc += wpet[m] * wcol[m];

    __nv_bfloat16 hh, ll;
    bsplit(acc, hh, ll);
    g_WTh[n * 256 + t] = hh;
    g_WTl[n * 256 + t] = ll;
    float whv = Wh[t * 128 + j];
    bsplit(whv, hh, ll);
    g_WTh[n * 256 + 128 + t] = hh;
    g_WTl[n * 256 + 128 + t] = ll;

    if (t == 0) {
        float ba = bi[j] + bh[j];
        for (int m = 0; m < 128; m++) ba += bpe[m] * wcol[m];
        g_bbig[n] = ba;
    }
}

// ---------------------------------------------------------------------------
// Init: es = X0@Wse + bse ; zero h layouts & c ; Xi = X0 ; out t=0 ; reset bar
// ---------------------------------------------------------------------------
__global__ void k_init(const float* __restrict__ X, const float* __restrict__ Wse,
                       const float* __restrict__ bse, float* __restrict__ out) {
    int row = blockIdx.x;
    int t = threadIdx.x;
    if (row == 0 && t == 0) { g_count = 0u; g_sense = 0u; }
    __shared__ float x0[64];
    if (t < 64) {
        float v = X[(size_t)row * 4096 + t];
        x0[t] = v;
        g_Xi[row * 64 + t] = v;
        out[(size_t)row * 4096 + t] = v;
    }
    __syncthreads();
    float acc = bse[t];
#pragma unroll 8
    for (int k = 0; k < 64; k++) acc += x0[k] * Wse[k * 128 + t];
    g_es[row * 128 + t] = acc;

    __nv_bfloat16 z = __float2bfloat16(0.f);
    g_hrh[0][(size_t)row * 128 + t] = z;
    g_hrl[0][(size_t)row * 128 + t] = z;
    int bb = row >> 9, nn = row & 511;
    g_hTh[0][(size_t)(bb * 128 + t) * 512 + nn] = z;
    g_hTl[0][(size_t)(bb * 128 + t) * 512 + nn] = z;
    g_c[row * 128 + t] = 0.f;
}

// ---------------------------------------------------------------------------
// k_ges: Ges = es @ Wes + bbig (4096 x 512, K=128) fp32, runs once
// ---------------------------------------------------------------------------
__global__ void __launch_bounds__(256) k_ges() {
    int m0 = (blockIdx.x >> 2) * 64;
    int n0 = (blockIdx.x & 3) * 128;

    __shared__ __align__(16) float As[16][68];
    __shared__ __align__(16) float Bs[16][132];

    int tid = threadIdx.x;
    int ty = tid >> 4, tx = tid & 15;
    int ar = tid >> 2, ac = (tid & 3) * 4;
    int br = tid >> 5, bc = (tid & 31) * 4;

    float acc[4][8] = {};

    for (int k0 = 0; k0 < 128; k0 += 16) {
        float4 av = *(const float4*)&g_es[(size_t)(m0 + ar) * 128 + k0 + ac];
        float4 bv0 = *(const float4*)&g_Wes[(size_t)(k0 + br) * 512 + n0 + bc];
        float4 bv1 = *(const float4*)&g_Wes[(size_t)(k0 + br + 8) * 512 + n0 + bc];
        As[ac + 0][ar] = av.x; As[ac + 1][ar] = av.y;
        As[ac + 2][ar] = av.z; As[ac + 3][ar] = av.w;
        *(float4*)&Bs[br][bc] = bv0;
        *(float4*)&Bs[br + 8][bc] = bv1;
        __syncthreads();
#pragma unroll
        for (int kk = 0; kk < 16; kk++) {
            float4 a4 = *(const float4*)&As[kk][ty * 4];
            float4 b0 = *(const float4*)&Bs[kk][tx * 8];
            float4 b1 = *(const float4*)&Bs[kk][tx * 8 + 4];
            float av4[4] = { a4.x, a4.y, a4.z, a4.w };
            float bv8[8] = { b0.x, b0.y, b0.z, b0.w, b1.x, b1.y, b1.z, b1.w };
#pragma unroll
            for (int i = 0; i < 4; i++)
#pragma unroll
                for (int jq = 0; jq < 8; jq++) acc[i][jq] += av4[i] * bv8[jq];
        }
        __syncthreads();
    }

    float bb[8];
#pragma unroll
    for (int q = 0; q < 8; q++) bb[q] = g_bbig[n0 + tx * 8 + q];
#pragma unroll
    for (int r = 0; r < 4; r++) {
        int rr = m0 + ty * 4 + r;
        float* dst = &g_Ges[(size_t)rr * 512 + n0 + tx * 8];
#pragma unroll
        for (int q = 0; q < 8; q++) dst[q] = acc[r][q] + bb[q];
    }
}

// ---------------------------------------------------------------------------
// phase gH: H = An @ h, CTA tile 64x64 (8b x 8m x 2n = 128 tiles)
// 8 warps 2m x 4n -> warp 32x16. K=512 x 3 phases, chunks of 64 -> 24 chunks.
// smem stages: A 64xRS + B 64xRS = 18432 per stage, double buffered.
// ---------------------------------------------------------------------------
__device__ __forceinline__ void phase_gH(char* dsm, int hin, int cta, int tid) {
    uint32_t sbase = smem_u32(dsm);
    const uint32_t AB = 64 * RS;           // 9216
    const uint32_t STG = 2 * 64 * RS;      // 18432
    int wid = tid >> 5, lane = tid & 31;
    int wm = wid >> 2, wn = wid & 3;
    int b  = cta >> 4;
    int m0 = ((cta >> 1) & 7) * 64;
    int n0 = (cta & 1) * 64;

    float acc[2][2][4];
#pragma unroll
    for (int i = 0; i < 2; i++)
#pragma unroll
        for (int j = 0; j < 2; j++)
#pragma unroll
            for (int q = 0; q < 4; q++) acc[i][j][q] = 0.f;

    auto issue = [&](int cc, uint32_t buf) {
        int ph = cc >> 3, kc = (cc & 7) * 64;
        const __nv_bfloat16* As = ((ph == 1) ? g_Anl : g_Anh)
            + (size_t)b * 262144 + (size_t)m0 * 512 + kc;
        const __nv_bfloat16* Bs = ((ph == 2) ? g_hTl[hin] : g_hTh[hin])
            + (size_t)b * 65536 + (size_t)n0 * 512 + kc;
#pragma unroll
        for (int i = 0; i < 2; i++) {
            int idx = tid + i * 256, r = idx >> 3, c = idx & 7;
            cpa16(buf + r * RS + c * 16, As + (size_t)r * 512 + c * 8);
        }
#pragma unroll
        for (int i = 0; i < 2; i++) {
            int idx = tid + i * 256, r = idx >> 3, c = idx & 7;
            cpa16(buf + AB + r * RS + c * 16, Bs + (size_t)r * 512 + c * 8);
        }
    };

    issue(0, sbase);
    CP_COMMIT();

#pragma unroll 1
    for (int cc = 0; cc < 24; cc++) {
        if (cc + 1 < 24) issue(cc + 1, sbase + ((cc + 1) & 1) * STG);
        CP_COMMIT();
        CP_WAIT1();
        __syncthreads();

        uint32_t bufA = sbase + (cc & 1) * STG;
        uint32_t bufB = bufA + AB;
        uint32_t aBase = bufA + (uint32_t)(wm * 32 + (lane & 15)) * RS + ((lane >> 4) * 16);
        uint32_t bBase = bufB + (uint32_t)(wn * 16 + (lane & 7) + ((lane >> 4) & 1) * 8) * RS
                              + (((lane >> 3) & 1) * 16);
#pragma unroll
        for (int ks = 0; ks < 4; ks++) {
            uint32_t a[2][4], bf[4];
            ldsm4(a[0], aBase + ks * 32);
            ldsm4(a[1], aBase + 16 * RS + ks * 32);
            ldsm4(bf, bBase + ks * 32);
#pragma unroll
            for (int mf = 0; mf < 2; mf++) {
                mmabf(acc[mf][0], a[mf], &bf[0]);
                mmabf(acc[mf][1], a[mf], &bf[2]);
            }
        }
        __syncthreads();
    }
    CP_WAIT0();

    int rbase = b * 512 + m0 + wm * 32 + (lane >> 2);
    int cbase = n0 + wn * 16 + (lane & 3) * 2;
#pragma unroll
    for (int mf = 0; mf < 2; mf++) {
#pragma unroll
        for (int nf = 0; nf < 2; nf++) {
            int col = cbase + nf * 8;
            float* d = acc[mf][nf];
            __nv_bfloat16 h0, l0, h1, l1;
            int r0 = rbase + mf * 16;
            bsplit(d[0], h0, l0); bsplit(d[1], h1, l1);
            *(__nv_bfloat162*)(g_Hh + (size_t)r0 * 128 + col) = __nv_bfloat162(h0, h1);
            *(__nv_bfloat162*)(g_Hl + (size_t)r0 * 128 + col) = __nv_bfloat162(l0, l1);
            bsplit(d[2], h0, l0); bsplit(d[3], h1, l1);
            *(__nv_bfloat162*)(g_Hh + (size_t)(r0 + 8) * 128 + col) = __nv_bfloat162(h0, h1);
            *(__nv_bfloat162*)(g_Hl + (size_t)(r0 + 8) * 128 + col) = __nv_bfloat162(l0, l1);
        }
    }
}

// ---------------------------------------------------------------------------
// phase gG: gates = Ges + [H | h] @ Wcomb (32m x 4n = 128 tiles of 128x128),
// 8 warps 2m x 4n -> warp 64x32. Fused LSTM epilogue.
// ---------------------------------------------------------------------------
__device__ __forceinline__ void phase_gG(char* dsm, int hin, int hout, int cta, int tid) {
    uint32_t sbase = smem_u32(dsm);
    const uint32_t AB = 128 * RS;          // 18432
    const uint32_t STG = 2 * 128 * RS;     // 36864
    int wid = tid >> 5, lane = tid & 31;
    int wm = wid >> 2, wn = wid & 3;
    int m0 = (cta >> 2) * 128;
    int n0 = (cta & 3) * 128;

    float acc[4][4][4];
#pragma unroll
    for (int i = 0; i < 4; i++)
#pragma unroll
        for (int j = 0; j < 4; j++)
#pragma unroll
            for (int q = 0; q < 4; q++) acc[i][j][q] = 0.f;

    auto issue = [&](int cc, uint32_t buf) {
        int ph = cc >> 2, kk = (cc & 3) * 64;
        const __nv_bfloat16* As;
        if (kk < 128)
            As = ((ph == 1) ? g_Hl : g_Hh) + (size_t)m0 * 128 + kk;
        else
            As = ((ph == 1) ? g_hrl[hin] : g_hrh[hin]) + (size_t)m0 * 128 + (kk - 128);
        const __nv_bfloat16* Bs = ((ph == 2) ? g_WTl : g_WTh) + (size_t)n0 * 256 + kk;
#pragma unroll
        for (int i = 0; i < 4; i++) {
            int idx = tid + i * 256, r = idx >> 3, c = idx & 7;
            cpa16(buf + r * RS + c * 16, As + (size_t)r * 128 + c * 8);
        }
#pragma unroll
        for (int i = 0; i < 4; i++) {
            int idx = tid + i * 256, r = idx >> 3, c = idx & 7;
            cpa16(buf + AB + r * RS + c * 16, Bs + (size_t)r * 256 + c * 8);
        }
    };

    issue(0, sbase);
    CP_COMMIT();

#pragma unroll 1
    for (int cc = 0; cc < 12; cc++) {
        if (cc + 1 < 12) issue(cc + 1, sbase + ((cc + 1) & 1) * STG);
        CP_COMMIT();
        CP_WAIT1();
        __syncthreads();

        uint32_t bufA = sbase + (cc & 1) * STG;
        uint32_t bufB = bufA + AB;
        uint32_t aBase = bufA + (uint32_t)(wm * 64 + (lane & 15)) * RS + ((lane >> 4) * 16);
        uint32_t bBase = bufB + (uint32_t)(wn * 32 + (lane & 7) + ((lane >> 4) & 1) * 8) * RS
                              + (((lane >> 3) & 1) * 16);
#pragma unroll
        for (int ks = 0; ks < 4; ks++) {
            uint32_t a[4][4], b0[4], b1[4];
            ldsm4(a[0], aBase + ks * 32);
            ldsm4(a[1], aBase + 16 * RS + ks * 32);
            ldsm4(a[2], aBase + 32 * RS + ks * 32);
            ldsm4(a[3], aBase + 48 * RS + ks * 32);
            ldsm4(b0, bBase + ks * 32);
            ldsm4(b1, bBase + 16 * RS + ks * 32);
#pragma unroll
            for (int mf = 0; mf < 4; mf++) {
                mmabf(acc[mf][0], a[mf], &b0[0]);
                mmabf(acc[mf][1], a[mf], &b0[2]);
                mmabf(acc[mf][2], a[mf], &b1[0]);
                mmabf(acc[mf][3], a[mf], &b1[2]);
            }
        }
        __syncthreads();
    }
    CP_WAIT0();
    __syncthreads();

    // stage fp32 tile in smem, then fused gate epilogue
    float* cst = (float*)dsm;   // [128][132] = 67584 B
#pragma unroll
    for (int mf = 0; mf < 4; mf++) {
#pragma unroll
        for (int nf = 0; nf < 4; nf++) {
            int row = wm * 64 + mf * 16 + (lane >> 2);
            int col = wn * 32 + nf * 8 + (lane & 3) * 2;
            float* d = acc[mf][nf];
            *(float2*)&cst[row * 132 + col]       = make_float2(d[0], d[1]);
            *(float2*)&cst[(row + 8) * 132 + col] = make_float2(d[2], d[3]);
        }
    }
    __syncthreads();

    __nv_bfloat16* hTh = g_hTh[hout];
    __nv_bfloat16* hTl = g_hTl[hout];
    __nv_bfloat16* hrho = g_hrh[hout];
    __nv_bfloat16* hrlo = g_hrl[hout];
#pragma unroll
    for (int i = 0; i < 16; i++) {
        int idx = tid + i * 256;
        int r = idx >> 5, q = idx & 31;
        int rr = m0 + r;
        int j = (n0 >> 2) + q;
        float4 pv = *(float4*)&cst[r * 132 + q * 4];
        float4 ge = *(const float4*)&g_Ges[(size_t)rr * 512 + j * 4];
        float pi = pv.x + ge.x, pf = pv.y + ge.y, pg = pv.z + ge.z, po = pv.w + ge.w;
        float iv = sigm(pi), fv = sigm(pf), gv = tanhf(pg), ov = sigm(po);
        size_t cidx = (size_t)rr * 128 + j;
        float cc = fv * g_c[cidx] + iv * gv;
        g_c[cidx] = cc;
        float hv = ov * tanhf(cc);
        g_hf[cidx] = hv;
        __nv_bfloat16 hh, ll;
        bsplit(hv, hh, ll);
        hrho[cidx] = hh;
        hrlo[cidx] = ll;
        int bb = rr >> 9, nn = rr & 511;
        size_t tidx = (size_t)(bb * 128 + j) * 512 + nn;
        hTh[tidx] = hh;
        hTl[tidx] = ll;
    }
    __syncthreads();
}

// ---------------------------------------------------------------------------
// phase out: Xi += h @ Wout + bout ; emit out[:, :, t, :]  (32 rows / CTA)
// Ws persistent in smem; hs staged per call.
// ---------------------------------------------------------------------------
__device__ __forceinline__ void phase_out(char* dsm, int t, const float* __restrict__ bout,
                                          float* __restrict__ out, int cta, int tid) {
    const float* Ws = (const float*)(dsm + SM_WS);
    float* hs = (float*)(dsm + SM_HS);
    int row0 = cta * 32;
    __syncthreads();
    for (int i = tid; i < 32 * 128; i += 256)
        hs[i] = g_hf[(size_t)row0 * 128 + i];
    __syncthreads();
#pragma unroll
    for (int kq = 0; kq < 8; kq++) {
        int e  = tid + kq * 256;
        int rr = e >> 6;
        int d  = e & 63;
        int grow = row0 + rr;
        float acc = g_Xi[grow * 64 + d] + bout[d];
        const float* hrow = &hs[rr * 128];
#pragma unroll 8
        for (int kk = 0; kk < 128; kk++) acc += hrow[kk] * Ws[kk * 64 + d];
        g_Xi[grow * 64 + d] = acc;
        out[(size_t)grow * 4096 + t * 64 + d] = acc;
    }
    __syncthreads();
}

// ---------------------------------------------------------------------------
// k_main: persistent kernel, all 63 steps with grid barriers.
// Phase A: gH(t) + out(t-1).  barrier.  Phase B: gG(t).  barrier.
// ---------------------------------------------------------------------------
__global__ void __launch_bounds__(256) k_main(const float* __restrict__ Wout,
                                              const float* __restrict__ bout,
                                              float* __restrict__ out) {
    extern __shared__ __align__(16) char dsm[];
    int cta = blockIdx.x, tid = threadIdx.x;

    // load Wout into persistent smem region once
    {
        float* Ws = (float*)(dsm + SM_WS);
        for (int i = tid; i < 128 * 64; i += 256) Ws[i] = Wout[i];
    }
    __syncthreads();

    unsigned gen = 0;
#pragma unroll 1
    for (int t = 1; t < Tc; t++) {
        int hin = (t - 1) & 1, hout = t & 1;
        phase_gH(dsm, hin, cta, tid);
        if (t >= 2) phase_out(dsm, t - 1, bout, out, cta, tid);
        gbar(++gen);
        phase_gG(dsm, hin, hout, cta, tid);
        gbar(++gen);
    }
    phase_out(dsm, Tc - 1, bout, out, cta, tid);
}

// ---------------------------------------------------------------------------
extern "C" void kernel_launch(void* const* d_in, const int* in_sizes, int n_in,
                              void* d_out, int out_size) {
    const float* X    = (const float*)d_in[0];
    const float* A    = (const float*)d_in[1];
    const float* Wse  = (const float*)d_in[2];
    const float* bse  = (const float*)d_in[3];
    const float* Wpe  = (const float*)d_in[4];
    const float* bpe  = (const float*)d_in[5];
    const float* Wii  = (const float*)d_in[6];
    const float* bii  = (const float*)d_in[7];
    const float* Whi  = (const float*)d_in[8];
    const float* bhi  = (const float*)d_in[9];
    const float* Wif  = (const float*)d_in[10];
    const float* bif_ = (const float*)d_in[11];
    const float* Whf  = (const float*)d_in[12];
    const float* bhf  = (const float*)d_in[13];
    const float* Wig  = (const float*)d_in[14];
    const float* big_ = (const float*)d_in[15];
    const float* Whg  = (const float*)d_in[16];
    const float* bhg  = (const float*)d_in[17];
    const float* Wio  = (const float*)d_in[18];
    const float* bio  = (const float*)d_in[19];
    const float* Who  = (const float*)d_in[20];
    const float* bho  = (const float*)d_in[21];
    const float* Wout = (const float*)d_in[22];
    const float* bout = (const float*)d_in[23];
    float* out = (float*)d_out;

    cudaFuncSetAttribute(k_main, cudaFuncAttributeMaxDynamicSharedMemorySize, SM_MAIN);

    k_dinv<<<Rc, 128>>>(A);
    k_an<<<2048, 256>>>(A);
    k_prep<<<512, 128>>>(Wii, bii, Whi, bhi, Wif, bif_, Whf, bhf,
                         Wig, big_, Whg, bhg, Wio, bio, Who, bho, Wpe, bpe);
    k_init<<<Rc, 128>>>(X, Wse, bse, out);
    k_ges<<<256, 256>>>();
    k_main<<<NCTA, 256, SM_MAIN>>>(Wout, bout, out);
}

// round 6
// speedup vs baseline: 2.3466x; 1.1314x over previous
#include <cuda_runtime.h>
#include <cuda_bf16.h>
#include <math.h>
#include <stdint.h>

// Problem constants
#define Bc   8
#define Nc   512
#define Tc   64
#define NINc 64
#define NHc  128
#define Rc   (Bc * Nc)   // 4096 rows
#define NCTA 128

// ---------------- scratch (device globals) ----------------------------------
__device__ float g_dinv[Rc];
__device__ __nv_bfloat16 g_Anh[Bc * Nc * Nc];   // An hi (4 MB)
__device__ __nv_bfloat16 g_Anl[Bc * Nc * Nc];   // An lo
__device__ float g_es[Rc * NHc];                // static embedding fp32
__device__ float g_Wes[128 * 512];              // Wi[0:128] interleaved fp32
__device__ float g_bbig[512];
__device__ float g_Ges[Rc * 512];               // es @ Wes + bbig (fp32, interleaved)
__device__ __nv_bfloat16 g_WTh[512 * 256];      // Wcomb^T hi: [n][k]
__device__ __nv_bfloat16 g_WTl[512 * 256];
__device__ __nv_bfloat16 g_Hh[Rc * NHc];        // H = An@h, hi/lo, row-major
__device__ __nv_bfloat16 g_Hl[Rc * NHc];
__device__ __nv_bfloat16 g_hrh[2][Rc * NHc];    // h row-major hi/lo (double buffered)
__device__ __nv_bfloat16 g_hrl[2][Rc * NHc];
__device__ __nv_bfloat16 g_hTh[2][Bc * NHc * Nc]; // h transposed per batch [b][j][n]
__device__ __nv_bfloat16 g_hTl[2][Bc * NHc * Nc];
__device__ float g_hf[Rc * NHc];                // h fp32 (for out phase)
__device__ float g_c[Rc * NHc];                 // cell state
__device__ float g_Xi[Rc * NINc];               // running output accumulator
__device__ unsigned g_count;                    // grid barrier arrive counter
__device__ unsigned g_sense;                    // grid barrier generation

// ---------------- helpers ----------------------------------------------------
__device__ __forceinline__ uint32_t smem_u32(const void* p) {
    uint32_t a;
    asm("{ .reg .u64 t; cvta.to.shared.u64 t, %1; cvt.u32.u64 %0, t; }" : "=r"(a) : "l"(p));
    return a;
}
__device__ __forceinline__ float sigm(float x) { return 1.f / (1.f + expf(-x)); }
__device__ __forceinline__ void bsplit(float v, __nv_bfloat16& hi, __nv_bfloat16& lo) {
    hi = __float2bfloat16(v);
    lo = __float2bfloat16(v - __bfloat162float(hi));
}
__device__ __forceinline__ void cpa16(uint32_t dst, const void* src) {
    asm volatile("cp.async.cg.shared.global [%0], [%1], 16;" :: "r"(dst), "l"(src) : "memory");
}
#define CP_COMMIT() asm volatile("cp.async.commit_group;" ::: "memory")
#define CP_WAIT1()  asm volatile("cp.async.wait_group 1;" ::: "memory")
#define CP_WAIT0()  asm volatile("cp.async.wait_group 0;" ::: "memory")

__device__ __forceinline__ void ldsm4(uint32_t* r, uint32_t a) {
    asm volatile("ldmatrix.sync.aligned.m8n8.x4.shared.b16 {%0,%1,%2,%3}, [%4];"
        : "=r"(r[0]), "=r"(r[1]), "=r"(r[2]), "=r"(r[3]) : "r"(a));
}
__device__ __forceinline__ void mmabf(float* d, const uint32_t* a, const uint32_t* b) {
    asm volatile("mma.sync.aligned.m16n8k16.row.col.f32.bf16.bf16.f32 "
        "{%0,%1,%2,%3}, {%4,%5,%6,%7}, {%8,%9}, {%0,%1,%2,%3};"
        : "+f"(d[0]), "+f"(d[1]), "+f"(d[2]), "+f"(d[3])
        : "r"(a[0]), "r"(a[1]), "r"(a[2]), "r"(a[3]), "r"(b[0]), "r"(b[1]));
}

// grid-wide sense barrier (128 CTAs, all co-resident)
__device__ __forceinline__ void gbar(unsigned gen) {
    __syncthreads();
    if (threadIdx.x == 0) {
        unsigned prev;
        asm volatile("atom.release.gpu.add.u32 %0, [%1], %2;"
                     : "=r"(prev) : "l"(&g_count), "r"(1u) : "memory");
        if (prev == NCTA - 1) {
            g_count = 0u;
            asm volatile("st.release.gpu.u32 [%0], %1;" :: "l"(&g_sense), "r"(gen) : "memory");
        } else {
            unsigned s;
            do {
                asm volatile("ld.acquire.gpu.u32 %0, [%1];" : "=r"(s) : "l"(&g_sense) : "memory");
            } while (s < gen);
        }
    }
    __syncthreads();
}

#define RS 144        // stage tile row stride (72 bf16)
#define GH_T   9216   // gH tile: 64 rows x RS
#define GG_T   18432  // gG tile: 128 rows x RS
#define STG_SZ 36864  // stage size (both phases)
// dsm layout:
//   [0, 73728)              2 stages (gH: Ah|Al|Bh|Bl; gG: Ah|Al) / out-phase Ws+hs / gG epi cst
//   [73728, 73728+135168)   persistent WT slice: hi (67584) then lo (67584), row stride 528
#define SM_WT    73728
#define WT_RSB   528
#define WT_SZ    67584
#define SM_TOTAL (SM_WT + 2 * WT_SZ)   // 208896

// ---------------------------------------------------------------------------
__global__ void k_dinv(const float* __restrict__ A) {
    int row = blockIdx.x;
    const float* arow = A + (size_t)row * Nc;
    float s = 0.f;
    for (int j = threadIdx.x; j < Nc; j += blockDim.x) s += arow[j];
    __shared__ float sh[128];
    sh[threadIdx.x] = s;
    __syncthreads();
    for (int off = 64; off > 0; off >>= 1) {
        if (threadIdx.x < off) sh[threadIdx.x] += sh[threadIdx.x + off];
        __syncthreads();
    }
    if (threadIdx.x == 0) {
        float d = sh[0];
        g_dinv[row] = (d > 0.f) ? rsqrtf(d) : 0.f;
    }
}

__global__ void k_an(const float* __restrict__ A) {
    int idx = blockIdx.x * blockDim.x + threadIdx.x;
    int e = idx * 4;
    int b   = e >> 18;
    int rem = e & 262143;
    int i   = rem >> 9;
    int j   = rem & 511;
    float4 a = *(const float4*)(A + (size_t)e);
    float di = g_dinv[b * 512 + i];
    const float* dj = g_dinv + b * 512 + j;
    float v[4] = { a.x * di * dj[0], a.y * di * dj[1], a.z * di * dj[2], a.w * di * dj[3] };
    __nv_bfloat16 h[4], l[4];
#pragma unroll
    for (int q = 0; q < 4; q++) bsplit(v[q], h[q], l[q]);
    __nv_bfloat162* ph = (__nv_bfloat162*)(g_Anh + (size_t)e);
    __nv_bfloat162* pl = (__nv_bfloat162*)(g_Anl + (size_t)e);
    ph[0] = __nv_bfloat162(h[0], h[1]); ph[1] = __nv_bfloat162(h[2], h[3]);
    pl[0] = __nv_bfloat162(l[0], l[1]); pl[1] = __nv_bfloat162(l[2], l[3]);
}

// ---------------------------------------------------------------------------
__global__ void k_prep(const float* __restrict__ Wii, const float* __restrict__ bii,
                       const float* __restrict__ Whi, const float* __restrict__ bhi,
                       const float* __restrict__ Wif, const float* __restrict__ bif_,
                       const float* __restrict__ Whf, const float* __restrict__ bhf,
                       const float* __restrict__ Wig, const float* __restrict__ big_,
                       const float* __restrict__ Whg, const float* __restrict__ bhg,
                       const float* __restrict__ Wio, const float* __restrict__ bio,
                       const float* __restrict__ Who, const float* __restrict__ bho,
                       const float* __restrict__ Wpe, const float* __restrict__ bpe) {
    int n = blockIdx.x;
    int g = n & 3;
    int j = n >> 2;
    int t = threadIdx.x;
    const float* Wi = (g == 0) ? Wii : (g == 1) ? Wif : (g == 2) ? Wig : Wio;
    const float* Wh = (g == 0) ? Whi : (g == 1) ? Whf : (g == 2) ? Whg : Who;
    const float* bi = (g == 0) ? bii : (g == 1) ? bif_ : (g == 2) ? big_ : bio;
    const float* bh = (g == 0) ? bhi : (g == 1) ? bhf : (g == 2) ? bhg : bho;

    __shared__ float wcol[128];
    wcol[t] = Wi[(128 + t) * 128 + j];
    __syncthreads();

    g_Wes[t * 512 + n] = Wi[t * 128 + j];

    float acc = 0.f;
    const float* wpet = Wpe + t * 128;
#pragma unroll 8
    for (int m = 0; m < 128; m++) acc += wpet[m] * wcol[m];

    __nv_bfloat16 hh, ll;
    bsplit(acc, hh, ll);
    g_WTh[n * 256 + t] = hh;
    g_WTl[n * 256 + t] = ll;
    float whv = Wh[t * 128 + j];
    bsplit(whv, hh, ll);
    g_WTh[n * 256 + 128 + t] = hh;
    g_WTl[n * 256 + 128 + t] = ll;

    if (t == 0) {
        float ba = bi[j] + bh[j];
        for (int m = 0; m < 128; m++) ba += bpe[m] * wcol[m];
        g_bbig[n] = ba;
    }
}

// ---------------------------------------------------------------------------
__global__ void k_init(const float* __restrict__ X, const float* __restrict__ Wse,
                       const float* __restrict__ bse, float* __restrict__ out) {
    int row = blockIdx.x;
    int t = threadIdx.x;
    if (row == 0 && t == 0) { g_count = 0u; g_sense = 0u; }
    __shared__ float x0[64];
    if (t < 64) {
        float v = X[(size_t)row * 4096 + t];
        x0[t] = v;
        g_Xi[row * 64 + t] = v;
        out[(size_t)row * 4096 + t] = v;
    }
    __syncthreads();
    float acc = bse[t];
#pragma unroll 8
    for (int k = 0; k < 64; k++) acc += x0[k] * Wse[k * 128 + t];
    g_es[row * 128 + t] = acc;

    __nv_bfloat16 z = __float2bfloat16(0.f);
    g_hrh[0][(size_t)row * 128 + t] = z;
    g_hrl[0][(size_t)row * 128 + t] = z;
    int bb = row >> 9, nn = row & 511;
    g_hTh[0][(size_t)(bb * 128 + t) * 512 + nn] = z;
    g_hTl[0][(size_t)(bb * 128 + t) * 512 + nn] = z;
    g_c[row * 128 + t] = 0.f;
}

// ---------------------------------------------------------------------------
// k_ges: Ges = es @ Wes + bbig (4096 x 512, K=128) fp32, runs once
// ---------------------------------------------------------------------------
__global__ void __launch_bounds__(256) k_ges() {
    int m0 = (blockIdx.x >> 2) * 64;
    int n0 = (blockIdx.x & 3) * 128;

    __shared__ __align__(16) float As[16][68];
    __shared__ __align__(16) float Bs[16][132];

    int tid = threadIdx.x;
    int ty = tid >> 4, tx = tid & 15;
    int ar = tid >> 2, ac = (tid & 3) * 4;
    int br = tid >> 5, bc = (tid & 31) * 4;

    float acc[4][8] = {};

    for (int k0 = 0; k0 < 128; k0 += 16) {
        float4 av = *(const float4*)&g_es[(size_t)(m0 + ar) * 128 + k0 + ac];
        float4 bv0 = *(const float4*)&g_Wes[(size_t)(k0 + br) * 512 + n0 + bc];
        float4 bv1 = *(const float4*)&g_Wes[(size_t)(k0 + br + 8) * 512 + n0 + bc];
        As[ac + 0][ar] = av.x; As[ac + 1][ar] = av.y;
        As[ac + 2][ar] = av.z; As[ac + 3][ar] = av.w;
        *(float4*)&Bs[br][bc] = bv0;
        *(float4*)&Bs[br + 8][bc] = bv1;
        __syncthreads();
#pragma unroll
        for (int kk = 0; kk < 16; kk++) {
            float4 a4 = *(const float4*)&As[kk][ty * 4];
            float4 b0 = *(const float4*)&Bs[kk][tx * 8];
            float4 b1 = *(const float4*)&Bs[kk][tx * 8 + 4];
            float av4[4] = { a4.x, a4.y, a4.z, a4.w };
            float bv8[8] = { b0.x, b0.y, b0.z, b0.w, b1.x, b1.y, b1.z, b1.w };
#pragma unroll
            for (int i = 0; i < 4; i++)
#pragma unroll
                for (int jq = 0; jq < 8; jq++) acc[i][jq] += av4[i] * bv8[jq];
        }
        __syncthreads();
    }

    float bb[8];
#pragma unroll
    for (int q = 0; q < 8; q++) bb[q] = g_bbig[n0 + tx * 8 + q];
#pragma unroll
    for (int r = 0; r < 4; r++) {
        int rr = m0 + ty * 4 + r;
        float* dst = &g_Ges[(size_t)rr * 512 + n0 + tx * 8];
#pragma unroll
        for (int q = 0; q < 8; q++) dst[q] = acc[r][q] + bb[q];
    }
}

// ---------------------------------------------------------------------------
// phase gH: H = An @ h, CTA tile 64x64 (8b x 8m x 2n = 128 tiles)
// Fused 3-product chunks: per 64-wide k chunk load Ah|Al|Bh|Bl, 3 MMA passes.
// 8 chunks. 8 warps 2m x 4n -> warp 32x16.
// ---------------------------------------------------------------------------
__device__ __forceinline__ void phase_gH(char* dsm, int hin, int cta, int tid) {
    uint32_t sbase = smem_u32(dsm);
    int wid = tid >> 5, lane = tid & 31;
    int wm = wid >> 2, wn = wid & 3;
    int b  = cta >> 4;
    int m0 = ((cta >> 1) & 7) * 64;
    int n0 = (cta & 1) * 64;

    float acc[2][2][4];
#pragma unroll
    for (int i = 0; i < 2; i++)
#pragma unroll
        for (int j = 0; j < 2; j++)
#pragma unroll
            for (int q = 0; q < 4; q++) acc[i][j][q] = 0.f;

    const __nv_bfloat16* Ah0 = g_Anh + (size_t)b * 262144 + (size_t)m0 * 512;
    const __nv_bfloat16* Al0 = g_Anl + (size_t)b * 262144 + (size_t)m0 * 512;
    const __nv_bfloat16* Bh0 = g_hTh[hin] + (size_t)b * 65536 + (size_t)n0 * 512;
    const __nv_bfloat16* Bl0 = g_hTl[hin] + (size_t)b * 65536 + (size_t)n0 * 512;

    auto issue = [&](int cc, uint32_t buf) {
        int kc = cc * 64;
#pragma unroll
        for (int i = 0; i < 2; i++) {
            int idx = tid + i * 256, r = idx >> 3, c = idx & 7;
            uint32_t d = buf + r * RS + c * 16;
            size_t off = (size_t)r * 512 + kc + c * 8;
            cpa16(d,            Ah0 + off);
            cpa16(d + GH_T,     Al0 + off);
            cpa16(d + 2 * GH_T, Bh0 + off);
            cpa16(d + 3 * GH_T, Bl0 + off);
        }
    };

    issue(0, sbase);
    CP_COMMIT();

#pragma unroll 1
    for (int cc = 0; cc < 8; cc++) {
        if (cc + 1 < 8) issue(cc + 1, sbase + ((cc + 1) & 1) * STG_SZ);
        CP_COMMIT();
        CP_WAIT1();
        __syncthreads();

        uint32_t buf = sbase + (cc & 1) * STG_SZ;
        uint32_t aH = buf + (uint32_t)(wm * 32 + (lane & 15)) * RS + ((lane >> 4) * 16);
        uint32_t aL = aH + GH_T;
        uint32_t bH = buf + 2 * GH_T
                    + (uint32_t)(wn * 16 + (lane & 7) + ((lane >> 4) & 1) * 8) * RS
                    + (((lane >> 3) & 1) * 16);
        uint32_t bL = bH + GH_T;
#pragma unroll
        for (int ks = 0; ks < 4; ks++) {
            uint32_t ah[2][4], al[2][4], bh[4], bl[4];
            ldsm4(ah[0], aH + ks * 32); ldsm4(ah[1], aH + 16 * RS + ks * 32);
            ldsm4(al[0], aL + ks * 32); ldsm4(al[1], aL + 16 * RS + ks * 32);
            ldsm4(bh, bH + ks * 32);
            ldsm4(bl, bL + ks * 32);
#pragma unroll
            for (int mf = 0; mf < 2; mf++) {
                mmabf(acc[mf][0], ah[mf], &bh[0]); mmabf(acc[mf][1], ah[mf], &bh[2]);
                mmabf(acc[mf][0], al[mf], &bh[0]); mmabf(acc[mf][1], al[mf], &bh[2]);
                mmabf(acc[mf][0], ah[mf], &bl[0]); mmabf(acc[mf][1], ah[mf], &bl[2]);
            }
        }
        __syncthreads();
    }
    CP_WAIT0();

    int rbase = b * 512 + m0 + wm * 32 + (lane >> 2);
    int cbase = n0 + wn * 16 + (lane & 3) * 2;
#pragma unroll
    for (int mf = 0; mf < 2; mf++) {
#pragma unroll
        for (int nf = 0; nf < 2; nf++) {
            int col = cbase + nf * 8;
            float* d = acc[mf][nf];
            __nv_bfloat16 h0, l0, h1, l1;
            int r0 = rbase + mf * 16;
            bsplit(d[0], h0, l0); bsplit(d[1], h1, l1);
            *(__nv_bfloat162*)(g_Hh + (size_t)r0 * 128 + col) = __nv_bfloat162(h0, h1);
            *(__nv_bfloat162*)(g_Hl + (size_t)r0 * 128 + col) = __nv_bfloat162(l0, l1);
            bsplit(d[2], h0, l0); bsplit(d[3], h1, l1);
            *(__nv_bfloat162*)(g_Hh + (size_t)(r0 + 8) * 128 + col) = __nv_bfloat162(h0, h1);
            *(__nv_bfloat162*)(g_Hl + (size_t)(r0 + 8) * 128 + col) = __nv_bfloat162(l0, l1);
        }
    }
}

// ---------------------------------------------------------------------------
// phase gG: gates = Ges + [H | h] @ Wcomb, 128x128 tiles (32m x 4n).
// B (weights) persistent in smem. A (Hh/Hl, h) streamed: 4 chunks of k=64,
// fused 3-product. Warp tile 64x32. Fused LSTM epilogue.
// ---------------------------------------------------------------------------
__device__ __forceinline__ void phase_gG(char* dsm, int hin, int hout, int cta, int tid) {
    uint32_t sbase = smem_u32(dsm);
    int wid = tid >> 5, lane = tid & 31;
    int wm = wid >> 2, wn = wid & 3;
    int m0 = (cta >> 2) * 128;
    int n0 = (cta & 3) * 128;

    float acc[4][4][4];
#pragma unroll
    for (int i = 0; i < 4; i++)
#pragma unroll
        for (int j = 0; j < 4; j++)
#pragma unroll
            for (int q = 0; q < 4; q++) acc[i][j][q] = 0.f;

    auto issue = [&](int cc, uint32_t buf) {
        int kc = cc * 64;
        const __nv_bfloat16* Ahs;
        const __nv_bfloat16* Als;
        if (kc < 128) {
            Ahs = g_Hh + (size_t)m0 * 128 + kc;
            Als = g_Hl + (size_t)m0 * 128 + kc;
        } else {
            Ahs = g_hrh[hin] + (size_t)m0 * 128 + (kc - 128);
            Als = g_hrl[hin] + (size_t)m0 * 128 + (kc - 128);
        }
#pragma unroll
        for (int i = 0; i < 4; i++) {
            int idx = tid + i * 256, r = idx >> 3, c = idx & 7;
            uint32_t d = buf + r * RS + c * 16;
            size_t off = (size_t)r * 128 + c * 8;
            cpa16(d,        Ahs + off);
            cpa16(d + GG_T, Als + off);
        }
    };

    issue(0, sbase);
    CP_COMMIT();

    uint32_t wtH = sbase + SM_WT
                 + (uint32_t)(wn * 32 + (lane & 7) + ((lane >> 4) & 1) * 8) * WT_RSB
                 + (((lane >> 3) & 1) * 16);
    uint32_t wtL = wtH + WT_SZ;

#pragma unroll 1
    for (int cc = 0; cc < 4; cc++) {
        if (cc + 1 < 4) issue(cc + 1, sbase + ((cc + 1) & 1) * STG_SZ);
        CP_COMMIT();
        CP_WAIT1();
        __syncthreads();

        uint32_t buf = sbase + (cc & 1) * STG_SZ;
        uint32_t aH = buf + (uint32_t)(wm * 64 + (lane & 15)) * RS + ((lane >> 4) * 16);
        uint32_t aL = aH + GG_T;
        uint32_t kb = (uint32_t)cc * 128;   // byte offset into persistent WT rows
#pragma unroll
        for (int ks = 0; ks < 4; ks++) {
            uint32_t ah[4][4], al[4][4], bh0[4], bh1[4], bl0[4], bl1[4];
#pragma unroll
            for (int mf = 0; mf < 4; mf++) {
                ldsm4(ah[mf], aH + mf * 16 * RS + ks * 32);
                ldsm4(al[mf], aL + mf * 16 * RS + ks * 32);
            }
            ldsm4(bh0, wtH + kb + ks * 32);
            ldsm4(bh1, wtH + 16 * WT_RSB + kb + ks * 32);
            ldsm4(bl0, wtL + kb + ks * 32);
            ldsm4(bl1, wtL + 16 * WT_RSB + kb + ks * 32);
#pragma unroll
            for (int mf = 0; mf < 4; mf++) {
                mmabf(acc[mf][0], ah[mf], &bh0[0]); mmabf(acc[mf][1], ah[mf], &bh0[2]);
                mmabf(acc[mf][2], ah[mf], &bh1[0]); mmabf(acc[mf][3], ah[mf], &bh1[2]);
                mmabf(acc[mf][0], al[mf], &bh0[0]); mmabf(acc[mf][1], al[mf], &bh0[2]);
                mmabf(acc[mf][2], al[mf], &bh1[0]); mmabf(acc[mf][3], al[mf], &bh1[2]);
                mmabf(acc[mf][0], ah[mf], &bl0[0]); mmabf(acc[mf][1], ah[mf], &bl0[2]);
                mmabf(acc[mf][2], ah[mf], &bl1[0]); mmabf(acc[mf][3], ah[mf], &bl1[2]);
            }
        }
        __syncthreads();
    }
    CP_WAIT0();
    __syncthreads();

    // stage fp32 tile in smem (stage region), fused gate epilogue
    float* cst = (float*)dsm;   // [128][132] = 67584 B <= 73728
#pragma unroll
    for (int mf = 0; mf < 4; mf++) {
#pragma unroll
        for (int nf = 0; nf < 4; nf++) {
            int row = wm * 64 + mf * 16 + (lane >> 2);
            int col = wn * 32 + nf * 8 + (lane & 3) * 2;
            float* d = acc[mf][nf];
            *(float2*)&cst[row * 132 + col]       = make_float2(d[0], d[1]);
            *(float2*)&cst[(row + 8) * 132 + col] = make_float2(d[2], d[3]);
        }
    }
    __syncthreads();

    __nv_bfloat16* hTh = g_hTh[hout];
    __nv_bfloat16* hTl = g_hTl[hout];
    __nv_bfloat16* hrho = g_hrh[hout];
    __nv_bfloat16* hrlo = g_hrl[hout];
#pragma unroll
    for (int i = 0; i < 16; i++) {
        int idx = tid + i * 256;
        int r = idx >> 5, q = idx & 31;
        int rr = m0 + r;
        int j = (n0 >> 2) + q;
        float4 pv = *(float4*)&cst[r * 132 + q * 4];
        float4 ge = *(const float4*)&g_Ges[(size_t)rr * 512 + j * 4];
        float pi = pv.x + ge.x, pf = pv.y + ge.y, pg = pv.z + ge.z, po = pv.w + ge.w;
        float iv = sigm(pi), fv = sigm(pf), gv = tanhf(pg), ov = sigm(po);
        size_t cidx = (size_t)rr * 128 + j;
        float cc = fv * g_c[cidx] + iv * gv;
        g_c[cidx] = cc;
        float hv = ov * tanhf(cc);
        g_hf[cidx] = hv;
        __nv_bfloat16 hh, ll;
        bsplit(hv, hh, ll);
        hrho[cidx] = hh;
        hrlo[cidx] = ll;
        int bb = rr >> 9, nn = rr & 511;
        size_t tidx = (size_t)(bb * 128 + j) * 512 + nn;
        hTh[tidx] = hh;
        hTl[tidx] = ll;
    }
    __syncthreads();
}

// ---------------------------------------------------------------------------
// phase out: Xi += h @ Wout + bout ; emit out[:, :, t, :]  (32 rows / CTA)
// Ws reloaded from L2 each step into stage region (cheap, L2-resident).
// ---------------------------------------------------------------------------
__device__ __forceinline__ void phase_out(char* dsm, int t, const float* __restrict__ Wout,
                                          const float* __restrict__ bout,
                                          float* __restrict__ out, int cta, int tid) {
    float* Ws = (float*)dsm;                 // 32768 B
    float* hs = (float*)(dsm + 32768);       // 16384 B
    int row0 = cta * 32;
    __syncthreads();
    for (int i = tid; i < 128 * 64; i += 256) Ws[i] = Wout[i];
    for (int i = tid; i < 32 * 128; i += 256)
        hs[i] = g_hf[(size_t)row0 * 128 + i];
    __syncthreads();
#pragma unroll
    for (int kq = 0; kq < 8; kq++) {
        int e  = tid + kq * 256;
        int rr = e >> 6;
        int d  = e & 63;
        int grow = row0 + rr;
        float acc = g_Xi[grow * 64 + d] + bout[d];
        const float* hrow = &hs[rr * 128];
#pragma unroll 8
        for (int kk = 0; kk < 128; kk++) acc += hrow[kk] * Ws[kk * 64 + d];
        g_Xi[grow * 64 + d] = acc;
        out[(size_t)grow * 4096 + t * 64 + d] = acc;
    }
    __syncthreads();
}

// ---------------------------------------------------------------------------
// k_main: persistent kernel, all 63 steps with grid barriers.
// Prologue: load WT n-slice into persistent smem.
// Phase A: gH(t) + out(t-1).  barrier.  Phase B: gG(t).  barrier.
// ---------------------------------------------------------------------------
__global__ void __launch_bounds__(256) k_main(const float* __restrict__ Wout,
                                              const float* __restrict__ bout,
                                              float* __restrict__ out) {
    extern __shared__ __align__(16) char dsm[];
    int cta = blockIdx.x, tid = threadIdx.x;

    // persistent weight slice for this CTA's gG n-tile
    {
        int n0 = (cta & 3) * 128;
        uint32_t wt = smem_u32(dsm) + SM_WT;
#pragma unroll
        for (int i = 0; i < 16; i++) {
            int idx = tid + i * 256;
            int r = idx >> 5, c = idx & 31;
            cpa16(wt + r * WT_RSB + c * 16,         g_WTh + (size_t)(n0 + r) * 256 + c * 8);
            cpa16(wt + WT_SZ + r * WT_RSB + c * 16, g_WTl + (size_t)(n0 + r) * 256 + c * 8);
        }
        CP_COMMIT();
        CP_WAIT0();
    }
    __syncthreads();

    unsigned gen = 0;
#pragma unroll 1
    for (int t = 1; t < Tc; t++) {
        int hin = (t - 1) & 1, hout = t & 1;
        phase_gH(dsm, hin, cta, tid);
        if (t >= 2) phase_out(dsm, t - 1, Wout, bout, out, cta, tid);
        gbar(++gen);
        phase_gG(dsm, hin, hout, cta, tid);
        gbar(++gen);
    }
    phase_out(dsm, Tc - 1, Wout, bout, out, cta, tid);
}

// ---------------------------------------------------------------------------
extern "C" void kernel_launch(void* const* d_in, const int* in_sizes, int n_in,
                              void* d_out, int out_size) {
    const float* X    = (const float*)d_in[0];
    const float* A    = (const float*)d_in[1];
    const float* Wse  = (const float*)d_in[2];
    const float* bse  = (const float*)d_in[3];
    const float* Wpe  = (const float*)d_in[4];
    const float* bpe  = (const float*)d_in[5];
    const float* Wii  = (const float*)d_in[6];
    const float* bii  = (const float*)d_in[7];
    const float* Whi  = (const float*)d_in[8];
    const float* bhi  = (const float*)d_in[9];
    const float* Wif  = (const float*)d_in[10];
    const float* bif_ = (const float*)d_in[11];
    const float* Whf  = (const float*)d_in[12];
    const float* bhf  = (const float*)d_in[13];
    const float* Wig  = (const float*)d_in[14];
    const float* big_ = (const float*)d_in[15];
    const float* Whg  = (const float*)d_in[16];
    const float* bhg  = (const float*)d_in[17];
    const float* Wio  = (const float*)d_in[18];
    const float* bio  = (const float*)d_in[19];
    const float* Who  = (const float*)d_in[20];
    const float* bho  = (const float*)d_in[21];
    const float* Wout = (const float*)d_in[22];
    const float* bout = (const float*)d_in[23];
    float* out = (float*)d_out;

    cudaFuncSetAttribute(k_main, cudaFuncAttributeMaxDynamicSharedMemorySize, SM_TOTAL);

    k_dinv<<<Rc, 128>>>(A);
    k_an<<<2048, 256>>>(A);
    k_prep<<<512, 128>>>(Wii, bii, Whi, bhi, Wif, bif_, Whf, bhf,
                         Wig, big_, Whg, bhg, Wio, bio, Who, bho, Wpe, bpe);
    k_init<<<Rc, 128>>>(X, Wse, bse, out);
    k_ges<<<256, 256>>>();
    k_main<<<NCTA, 256, SM_TOTAL>>>(Wout, bout, out);
}

// round 7
// speedup vs baseline: 3.7339x; 1.5912x over previous
#include <cuda_runtime.h>
#include <cuda_bf16.h>
#include <math.h>
#include <stdint.h>

// Problem constants
#define Bc   8
#define Nc   512
#define Tc   64
#define NINc 64
#define NHc  128
#define Rc   (Bc * Nc)   // 4096 rows
#define NCTA 128

// ---------------- scratch (device globals) ----------------------------------
__device__ float g_dinv[Rc];
__device__ __nv_bfloat16 g_Anh[Bc * Nc * Nc];   // An hi (4 MB)
__device__ __nv_bfloat16 g_Anl[Bc * Nc * Nc];   // An lo
__device__ float g_es[Rc * NHc];                // static embedding fp32
__device__ float g_Wes[128 * 512];              // Wi[0:128] interleaved fp32
__device__ float g_bbig[512];
__device__ float g_Ges[Rc * 512];               // es @ Wes + bbig (fp32, interleaved)
__device__ __nv_bfloat16 g_WTh[512 * 256];      // Wcomb^T hi: [n][k]
__device__ __nv_bfloat16 g_WTl[512 * 256];
__device__ __nv_bfloat16 g_WoTh[64 * 128];      // Wout^T hi: [n][k]
__device__ __nv_bfloat16 g_WoTl[64 * 128];
__device__ __nv_bfloat16 g_Hh[Rc * NHc];        // H = An@h, hi/lo, row-major
__device__ __nv_bfloat16 g_Hl[Rc * NHc];
__device__ __nv_bfloat16 g_hrh[2][Rc * NHc];    // h row-major hi/lo (double buffered)
__device__ __nv_bfloat16 g_hrl[2][Rc * NHc];
__device__ __nv_bfloat16 g_hTh[2][Bc * NHc * Nc]; // h transposed per batch [b][j][n]
__device__ __nv_bfloat16 g_hTl[2][Bc * NHc * Nc];
__device__ float g_c[Rc * NHc];                 // cell state
__device__ float g_Xi[Rc * NINc];               // running output accumulator
__device__ unsigned g_count;                    // grid barrier arrive counter
__device__ unsigned g_sense;                    // grid barrier generation

// ---------------- helpers ----------------------------------------------------
__device__ __forceinline__ uint32_t smem_u32(const void* p) {
    uint32_t a;
    asm("{ .reg .u64 t; cvta.to.shared.u64 t, %1; cvt.u32.u64 %0, t; }" : "=r"(a) : "l"(p));
    return a;
}
// fast sigmoid / tanh via MUFU paths (always-fast intrinsics, ~2 ulp)
__device__ __forceinline__ float sigm(float x) {
    return __fdividef(1.f, 1.f + __expf(-x));
}
__device__ __forceinline__ float ftanh(float x) {
    float e = __expf(2.f * x);
    return 1.f - __fdividef(2.f, e + 1.f);
}
__device__ __forceinline__ void bsplit(float v, __nv_bfloat16& hi, __nv_bfloat16& lo) {
    hi = __float2bfloat16(v);
    lo = __float2bfloat16(v - __bfloat162float(hi));
}
__device__ __forceinline__ void cpa16(uint32_t dst, const void* src) {
    asm volatile("cp.async.cg.shared.global [%0], [%1], 16;" :: "r"(dst), "l"(src) : "memory");
}
#define CP_COMMIT() asm volatile("cp.async.commit_group;" ::: "memory")
#define CP_WAIT1()  asm volatile("cp.async.wait_group 1;" ::: "memory")
#define CP_WAIT0()  asm volatile("cp.async.wait_group 0;" ::: "memory")

__device__ __forceinline__ void ldsm4(uint32_t* r, uint32_t a) {
    asm volatile("ldmatrix.sync.aligned.m8n8.x4.shared.b16 {%0,%1,%2,%3}, [%4];"
        : "=r"(r[0]), "=r"(r[1]), "=r"(r[2]), "=r"(r[3]) : "r"(a));
}
__device__ __forceinline__ void mmabf(float* d, const uint32_t* a, const uint32_t* b) {
    asm volatile("mma.sync.aligned.m16n8k16.row.col.f32.bf16.bf16.f32 "
        "{%0,%1,%2,%3}, {%4,%5,%6,%7}, {%8,%9}, {%0,%1,%2,%3};"
        : "+f"(d[0]), "+f"(d[1]), "+f"(d[2]), "+f"(d[3])
        : "r"(a[0]), "r"(a[1]), "r"(a[2]), "r"(a[3]), "r"(b[0]), "r"(b[1]));
}

// grid-wide sense barrier (128 CTAs, all co-resident)
__device__ __forceinline__ void gbar(unsigned gen) {
    __syncthreads();
    if (threadIdx.x == 0) {
        unsigned prev;
        asm volatile("atom.release.gpu.add.u32 %0, [%1], %2;"
                     : "=r"(prev) : "l"(&g_count), "r"(1u) : "memory");
        if (prev == NCTA - 1) {
            g_count = 0u;
            asm volatile("st.release.gpu.u32 [%0], %1;" :: "l"(&g_sense), "r"(gen) : "memory");
        } else {
            unsigned s;
            do {
                asm volatile("ld.acquire.gpu.u32 %0, [%1];" : "=r"(s) : "l"(&g_sense) : "memory");
            } while (s < gen);
        }
    }
    __syncthreads();
}

#define RS 144        // stage tile row stride (72 bf16)
#define GH_T   9216   // gH tile: 64 rows x RS
#define GG_T   18432  // gG tile: 128 rows x RS
#define STG_SZ 36864  // stage size (both phases)
// dsm layout:
//   [0, 73728)              2 stages / gG epi cst + transpose / out-phase tiles
//   [73728, 73728+135168)   persistent WT slice: hi then lo, row stride 528
#define SM_WT    73728
#define WT_RSB   528
#define WT_SZ    67584
#define SM_TOTAL (SM_WT + 2 * WT_SZ)   // 208896
// out-phase stage offsets (within [0,73728))
#define OUT_RSB  272
#define OUT_HA   0
#define OUT_HAL  8704
#define OUT_WB   17408
#define OUT_WBL  34816

// ---------------------------------------------------------------------------
__global__ void k_dinv(const float* __restrict__ A) {
    int row = blockIdx.x;
    const float* arow = A + (size_t)row * Nc;
    float s = 0.f;
    for (int j = threadIdx.x; j < Nc; j += blockDim.x) s += arow[j];
    __shared__ float sh[128];
    sh[threadIdx.x] = s;
    __syncthreads();
    for (int off = 64; off > 0; off >>= 1) {
        if (threadIdx.x < off) sh[threadIdx.x] += sh[threadIdx.x + off];
        __syncthreads();
    }
    if (threadIdx.x == 0) {
        float d = sh[0];
        g_dinv[row] = (d > 0.f) ? rsqrtf(d) : 0.f;
    }
}

__global__ void k_an(const float* __restrict__ A) {
    int idx = blockIdx.x * blockDim.x + threadIdx.x;
    int e = idx * 4;
    int b   = e >> 18;
    int rem = e & 262143;
    int i   = rem >> 9;
    int j   = rem & 511;
    float4 a = *(const float4*)(A + (size_t)e);
    float di = g_dinv[b * 512 + i];
    const float* dj = g_dinv + b * 512 + j;
    float v[4] = { a.x * di * dj[0], a.y * di * dj[1], a.z * di * dj[2], a.w * di * dj[3] };
    __nv_bfloat16 h[4], l[4];
#pragma unroll
    for (int q = 0; q < 4; q++) bsplit(v[q], h[q], l[q]);
    __nv_bfloat162* ph = (__nv_bfloat162*)(g_Anh + (size_t)e);
    __nv_bfloat162* pl = (__nv_bfloat162*)(g_Anl + (size_t)e);
    ph[0] = __nv_bfloat162(h[0], h[1]); ph[1] = __nv_bfloat162(h[2], h[3]);
    pl[0] = __nv_bfloat162(l[0], l[1]); pl[1] = __nv_bfloat162(l[2], l[3]);
}

// ---------------------------------------------------------------------------
__global__ void k_prep(const float* __restrict__ Wii, const float* __restrict__ bii,
                       const float* __restrict__ Whi, const float* __restrict__ bhi,
                       const float* __restrict__ Wif, const float* __restrict__ bif_,
                       const float* __restrict__ Whf, const float* __restrict__ bhf,
                       const float* __restrict__ Wig, const float* __restrict__ big_,
                       const float* __restrict__ Whg, const float* __restrict__ bhg,
                       const float* __restrict__ Wio, const float* __restrict__ bio,
                       const float* __restrict__ Who, const float* __restrict__ bho,
                       const float* __restrict__ Wpe, const float* __restrict__ bpe) {
    int n = blockIdx.x;
    int g = n & 3;
    int j = n >> 2;
    int t = threadIdx.x;
    const float* Wi = (g == 0) ? Wii : (g == 1) ? Wif : (g == 2) ? Wig : Wio;
    const float* Wh = (g == 0) ? Whi : (g == 1) ? Whf : (g == 2) ? Whg : Who;
    const float* bi = (g == 0) ? bii : (g == 1) ? bif_ : (g == 2) ? big_ : bio;
    const float* bh = (g == 0) ? bhi : (g == 1) ? bhf : (g == 2) ? bhg : bho;

    __shared__ float wcol[128];
    wcol[t] = Wi[(128 + t) * 128 + j];
    __syncthreads();

    g_Wes[t * 512 + n] = Wi[t * 128 + j];

    float acc = 0.f;
    const float* wpet = Wpe + t * 128;
#pragma unroll 8
    for (int m = 0; m < 128; m++) acc += wpet[m] * wcol[m];

    __nv_bfloat16 hh, ll;
    bsplit(acc, hh, ll);
    g_WTh[n * 256 + t] = hh;
    g_WTl[n * 256 + t] = ll;
    float whv = Wh[t * 128 + j];
    bsplit(whv, hh, ll);
    g_WTh[n * 256 + 128 + t] = hh;
    g_WTl[n * 256 + 128 + t] = ll;

    if (t == 0) {
        float ba = bi[j] + bh[j];
        for (int m = 0; m < 128; m++) ba += bpe[m] * wcol[m];
        g_bbig[n] = ba;
    }
}

// WoutT hi/lo: [n=64][k=128]
__global__ void k_prepout(const float* __restrict__ Wout) {
    int n = blockIdx.x;
    int k = threadIdx.x;
    __nv_bfloat16 hh, ll;
    bsplit(Wout[k * 64 + n], hh, ll);
    g_WoTh[n * 128 + k] = hh;
    g_WoTl[n * 128 + k] = ll;
}

// ---------------------------------------------------------------------------
__global__ void k_init(const float* __restrict__ X, const float* __restrict__ Wse,
                       const float* __restrict__ bse, float* __restrict__ out) {
    int row = blockIdx.x;
    int t = threadIdx.x;
    if (row == 0 && t == 0) { g_count = 0u; g_sense = 0u; }
    __shared__ float x0[64];
    if (t < 64) {
        float v = X[(size_t)row * 4096 + t];
        x0[t] = v;
        g_Xi[row * 64 + t] = v;
        out[(size_t)row * 4096 + t] = v;
    }
    __syncthreads();
    float acc = bse[t];
#pragma unroll 8
    for (int k = 0; k < 64; k++) acc += x0[k] * Wse[k * 128 + t];
    g_es[row * 128 + t] = acc;

    __nv_bfloat16 z = __float2bfloat16(0.f);
    g_hrh[0][(size_t)row * 128 + t] = z;
    g_hrl[0][(size_t)row * 128 + t] = z;
    int bb = row >> 9, nn = row & 511;
    g_hTh[0][(size_t)(bb * 128 + t) * 512 + nn] = z;
    g_hTl[0][(size_t)(bb * 128 + t) * 512 + nn] = z;
    g_c[row * 128 + t] = 0.f;
}

// ---------------------------------------------------------------------------
// k_ges: Ges = es @ Wes + bbig (4096 x 512, K=128) fp32, runs once
// ---------------------------------------------------------------------------
__global__ void __launch_bounds__(256) k_ges() {
    int m0 = (blockIdx.x >> 2) * 64;
    int n0 = (blockIdx.x & 3) * 128;

    __shared__ __align__(16) float As[16][68];
    __shared__ __align__(16) float Bs[16][132];

    int tid = threadIdx.x;
    int ty = tid >> 4, tx = tid & 15;
    int ar = tid >> 2, ac = (tid & 3) * 4;
    int br = tid >> 5, bc = (tid & 31) * 4;

    float acc[4][8] = {};

    for (int k0 = 0; k0 < 128; k0 += 16) {
        float4 av = *(const float4*)&g_es[(size_t)(m0 + ar) * 128 + k0 + ac];
        float4 bv0 = *(const float4*)&g_Wes[(size_t)(k0 + br) * 512 + n0 + bc];
        float4 bv1 = *(const float4*)&g_Wes[(size_t)(k0 + br + 8) * 512 + n0 + bc];
        As[ac + 0][ar] = av.x; As[ac + 1][ar] = av.y;
        As[ac + 2][ar] = av.z; As[ac + 3][ar] = av.w;
        *(float4*)&Bs[br][bc] = bv0;
        *(float4*)&Bs[br + 8][bc] = bv1;
        __syncthreads();
#pragma unroll
        for (int kk = 0; kk < 16; kk++) {
            float4 a4 = *(const float4*)&As[kk][ty * 4];
            float4 b0 = *(const float4*)&Bs[kk][tx * 8];
            float4 b1 = *(const float4*)&Bs[kk][tx * 8 + 4];
            float av4[4] = { a4.x, a4.y, a4.z, a4.w };
            float bv8[8] = { b0.x, b0.y, b0.z, b0.w, b1.x, b1.y, b1.z, b1.w };
#pragma unroll
            for (int i = 0; i < 4; i++)
#pragma unroll
                for (int jq = 0; jq < 8; jq++) acc[i][jq] += av4[i] * bv8[jq];
        }
        __syncthreads();
    }

    float bb[8];
#pragma unroll
    for (int q = 0; q < 8; q++) bb[q] = g_bbig[n0 + tx * 8 + q];
#pragma unroll
    for (int r = 0; r < 4; r++) {
        int rr = m0 + ty * 4 + r;
        float* dst = &g_Ges[(size_t)rr * 512 + n0 + tx * 8];
#pragma unroll
        for (int q = 0; q < 8; q++) dst[q] = acc[r][q] + bb[q];
    }
}

// ---------------------------------------------------------------------------
// phase gH: H = An @ h, CTA tile 64x64 (8b x 8m x 2n = 128 tiles)
// ---------------------------------------------------------------------------
__device__ __forceinline__ void phase_gH(char* dsm, int hin, int cta, int tid) {
    uint32_t sbase = smem_u32(dsm);
    int wid = tid >> 5, lane = tid & 31;
    int wm = wid >> 2, wn = wid & 3;
    int b  = cta >> 4;
    int m0 = ((cta >> 1) & 7) * 64;
    int n0 = (cta & 1) * 64;

    float acc[2][2][4];
#pragma unroll
    for (int i = 0; i < 2; i++)
#pragma unroll
        for (int j = 0; j < 2; j++)
#pragma unroll
            for (int q = 0; q < 4; q++) acc[i][j][q] = 0.f;

    const __nv_bfloat16* Ah0 = g_Anh + (size_t)b * 262144 + (size_t)m0 * 512;
    const __nv_bfloat16* Al0 = g_Anl + (size_t)b * 262144 + (size_t)m0 * 512;
    const __nv_bfloat16* Bh0 = g_hTh[hin] + (size_t)b * 65536 + (size_t)n0 * 512;
    const __nv_bfloat16* Bl0 = g_hTl[hin] + (size_t)b * 65536 + (size_t)n0 * 512;

    auto issue = [&](int cc, uint32_t buf) {
        int kc = cc * 64;
#pragma unroll
        for (int i = 0; i < 2; i++) {
            int idx = tid + i * 256, r = idx >> 3, c = idx & 7;
            uint32_t d = buf + r * RS + c * 16;
            size_t off = (size_t)r * 512 + kc + c * 8;
            cpa16(d,            Ah0 + off);
            cpa16(d + GH_T,     Al0 + off);
            cpa16(d + 2 * GH_T, Bh0 + off);
            cpa16(d + 3 * GH_T, Bl0 + off);
        }
    };

    issue(0, sbase);
    CP_COMMIT();

#pragma unroll 1
    for (int cc = 0; cc < 8; cc++) {
        if (cc + 1 < 8) issue(cc + 1, sbase + ((cc + 1) & 1) * STG_SZ);
        CP_COMMIT();
        CP_WAIT1();
        __syncthreads();

        uint32_t buf = sbase + (cc & 1) * STG_SZ;
        uint32_t aH = buf + (uint32_t)(wm * 32 + (lane & 15)) * RS + ((lane >> 4) * 16);
        uint32_t aL = aH + GH_T;
        uint32_t bH = buf + 2 * GH_T
                    + (uint32_t)(wn * 16 + (lane & 7) + ((lane >> 4) & 1) * 8) * RS
                    + (((lane >> 3) & 1) * 16);
        uint32_t bL = bH + GH_T;
#pragma unroll
        for (int ks = 0; ks < 4; ks++) {
            uint32_t ah[2][4], al[2][4], bh[4], bl[4];
            ldsm4(ah[0], aH + ks * 32); ldsm4(ah[1], aH + 16 * RS + ks * 32);
            ldsm4(al[0], aL + ks * 32); ldsm4(al[1], aL + 16 * RS + ks * 32);
            ldsm4(bh, bH + ks * 32);
            ldsm4(bl, bL + ks * 32);
#pragma unroll
            for (int mf = 0; mf < 2; mf++) {
                mmabf(acc[mf][0], ah[mf], &bh[0]); mmabf(acc[mf][1], ah[mf], &bh[2]);
                mmabf(acc[mf][0], al[mf], &bh[0]); mmabf(acc[mf][1], al[mf], &bh[2]);
                mmabf(acc[mf][0], ah[mf], &bl[0]); mmabf(acc[mf][1], ah[mf], &bl[2]);
            }
        }
        __syncthreads();
    }
    CP_WAIT0();

    int rbase = b * 512 + m0 + wm * 32 + (lane >> 2);
    int cbase = n0 + wn * 16 + (lane & 3) * 2;
#pragma unroll
    for (int mf = 0; mf < 2; mf++) {
#pragma unroll
        for (int nf = 0; nf < 2; nf++) {
            int col = cbase + nf * 8;
            float* d = acc[mf][nf];
            __nv_bfloat16 h0, l0, h1, l1;
            int r0 = rbase + mf * 16;
            bsplit(d[0], h0, l0); bsplit(d[1], h1, l1);
            *(__nv_bfloat162*)(g_Hh + (size_t)r0 * 128 + col) = __nv_bfloat162(h0, h1);
            *(__nv_bfloat162*)(g_Hl + (size_t)r0 * 128 + col) = __nv_bfloat162(l0, l1);
            bsplit(d[2], h0, l0); bsplit(d[3], h1, l1);
            *(__nv_bfloat162*)(g_Hh + (size_t)(r0 + 8) * 128 + col) = __nv_bfloat162(h0, h1);
            *(__nv_bfloat162*)(g_Hl + (size_t)(r0 + 8) * 128 + col) = __nv_bfloat162(l0, l1);
        }
    }
}

// ---------------------------------------------------------------------------
// phase gG: gates = Ges + [H | h] @ Wcomb, 128x128 tiles (32m x 4n).
// B persistent in smem; A streamed 4 chunks, fused 3-product.
// Epilogue: fast gate math, h kept in regs, smem transpose -> coalesced hT.
// ---------------------------------------------------------------------------
__device__ __forceinline__ void phase_gG(char* dsm, int hin, int hout, int cta, int tid) {
    uint32_t sbase = smem_u32(dsm);
    int wid = tid >> 5, lane = tid & 31;
    int wm = wid >> 2, wn = wid & 3;
    int m0 = (cta >> 2) * 128;
    int n0 = (cta & 3) * 128;

    float acc[4][4][4];
#pragma unroll
    for (int i = 0; i < 4; i++)
#pragma unroll
        for (int j = 0; j < 4; j++)
#pragma unroll
            for (int q = 0; q < 4; q++) acc[i][j][q] = 0.f;

    auto issue = [&](int cc, uint32_t buf) {
        int kc = cc * 64;
        const __nv_bfloat16* Ahs;
        const __nv_bfloat16* Als;
        if (kc < 128) {
            Ahs = g_Hh + (size_t)m0 * 128 + kc;
            Als = g_Hl + (size_t)m0 * 128 + kc;
        } else {
            Ahs = g_hrh[hin] + (size_t)m0 * 128 + (kc - 128);
            Als = g_hrl[hin] + (size_t)m0 * 128 + (kc - 128);
        }
#pragma unroll
        for (int i = 0; i < 4; i++) {
            int idx = tid + i * 256, r = idx >> 3, c = idx & 7;
            uint32_t d = buf + r * RS + c * 16;
            size_t off = (size_t)r * 128 + c * 8;
            cpa16(d,        Ahs + off);
            cpa16(d + GG_T, Als + off);
        }
    };

    issue(0, sbase);
    CP_COMMIT();

    uint32_t wtH = sbase + SM_WT
                 + (uint32_t)(wn * 32 + (lane & 7) + ((lane >> 4) & 1) * 8) * WT_RSB
                 + (((lane >> 3) & 1) * 16);
    uint32_t wtL = wtH + WT_SZ;

#pragma unroll 1
    for (int cc = 0; cc < 4; cc++) {
        if (cc + 1 < 4) issue(cc + 1, sbase + ((cc + 1) & 1) * STG_SZ);
        CP_COMMIT();
        CP_WAIT1();
        __syncthreads();

        uint32_t buf = sbase + (cc & 1) * STG_SZ;
        uint32_t aH = buf + (uint32_t)(wm * 64 + (lane & 15)) * RS + ((lane >> 4) * 16);
        uint32_t aL = aH + GG_T;
        uint32_t kb = (uint32_t)cc * 128;
#pragma unroll
        for (int ks = 0; ks < 4; ks++) {
            uint32_t ah[4][4], al[4][4], bh0[4], bh1[4], bl0[4], bl1[4];
#pragma unroll
            for (int mf = 0; mf < 4; mf++) {
                ldsm4(ah[mf], aH + mf * 16 * RS + ks * 32);
                ldsm4(al[mf], aL + mf * 16 * RS + ks * 32);
            }
            ldsm4(bh0, wtH + kb + ks * 32);
            ldsm4(bh1, wtH + 16 * WT_RSB + kb + ks * 32);
            ldsm4(bl0, wtL + kb + ks * 32);
            ldsm4(bl1, wtL + 16 * WT_RSB + kb + ks * 32);
#pragma unroll
            for (int mf = 0; mf < 4; mf++) {
                mmabf(acc[mf][0], ah[mf], &bh0[0]); mmabf(acc[mf][1], ah[mf], &bh0[2]);
                mmabf(acc[mf][2], ah[mf], &bh1[0]); mmabf(acc[mf][3], ah[mf], &bh1[2]);
                mmabf(acc[mf][0], al[mf], &bh0[0]); mmabf(acc[mf][1], al[mf], &bh0[2]);
                mmabf(acc[mf][2], al[mf], &bh1[0]); mmabf(acc[mf][3], al[mf], &bh1[2]);
                mmabf(acc[mf][0], ah[mf], &bl0[0]); mmabf(acc[mf][1], ah[mf], &bl0[2]);
                mmabf(acc[mf][2], ah[mf], &bl1[0]); mmabf(acc[mf][3], ah[mf], &bl1[2]);
            }
        }
        __syncthreads();
    }
    CP_WAIT0();
    __syncthreads();

    // stage fp32 gate tile in smem
    float* cst = (float*)dsm;   // [128][132] = 67584 B
#pragma unroll
    for (int mf = 0; mf < 4; mf++) {
#pragma unroll
        for (int nf = 0; nf < 4; nf++) {
            int row = wm * 64 + mf * 16 + (lane >> 2);
            int col = wn * 32 + nf * 8 + (lane & 3) * 2;
            float* d = acc[mf][nf];
            *(float2*)&cst[row * 132 + col]       = make_float2(d[0], d[1]);
            *(float2*)&cst[(row + 8) * 132 + col] = make_float2(d[2], d[3]);
        }
    }
    __syncthreads();

    // pass 1: gates -> c, h (h kept in regs); row-major coalesced writes only
    float hv16[16];
    int q  = tid & 31;           // fixed feature quad within n-slice
    int rb = tid >> 5;           // base row
    int j  = (n0 >> 2) + q;      // global feature index
    __nv_bfloat16* hrho = g_hrh[hout];
    __nv_bfloat16* hrlo = g_hrl[hout];
#pragma unroll
    for (int i = 0; i < 16; i++) {
        int r = rb + i * 8;
        int rr = m0 + r;
        float4 pv = *(float4*)&cst[r * 132 + q * 4];
        float4 ge = *(const float4*)&g_Ges[(size_t)rr * 512 + j * 4];
        float iv = sigm(pv.x + ge.x), fv = sigm(pv.y + ge.y);
        float gv = ftanh(pv.z + ge.z), ov = sigm(pv.w + ge.w);
        size_t cidx = (size_t)rr * 128 + j;
        float cc = fv * g_c[cidx] + iv * gv;
        g_c[cidx] = cc;
        float hv = ov * ftanh(cc);
        hv16[i] = hv;
        __nv_bfloat16 hh, ll;
        bsplit(hv, hh, ll);
        hrho[cidx] = hh;
        hrlo[cidx] = ll;
    }
    __syncthreads();   // cst dead

    // pass 2: smem transpose (32 features x 128 rows), reuse dsm
    __nv_bfloat16* trh = (__nv_bfloat16*)dsm;            // [32][136]
    __nv_bfloat16* trl = (__nv_bfloat16*)(dsm + 8704);
#pragma unroll
    for (int i = 0; i < 16; i++) {
        int r = rb + i * 8;
        __nv_bfloat16 hh, ll;
        bsplit(hv16[i], hh, ll);
        trh[q * 136 + r] = hh;
        trl[q * 136 + r] = ll;
    }
    __syncthreads();

    // pass 3: coalesced hT writes (rows of 256B)
    __nv_bfloat16* hTh = g_hTh[hout];
    __nv_bfloat16* hTl = g_hTl[hout];
    int bb = m0 >> 9, nn0 = m0 & 511;
    int jr = tid >> 4, ch = tid & 15;
#pragma unroll
    for (int half = 0; half < 2; half++) {
        int jj = jr + half * 16;
        uint4 vh = *(uint4*)&trh[jj * 136 + ch * 8];
        uint4 vl = *(uint4*)&trl[jj * 136 + ch * 8];
        size_t base = (size_t)(bb * 128 + (n0 >> 2) + jj) * 512 + nn0 + ch * 8;
        *(uint4*)&hTh[base] = vh;
        *(uint4*)&hTl[base] = vl;
    }
    __syncthreads();
}

// ---------------------------------------------------------------------------
// phase out (tensor-core): Xi += h @ Wout + bout ; emit out[:, :, t, :]
// M=32 (rows row0..+32), N=64, K=128, hi/lo 3-pass. h from hrh/hrl[hidx].
// ---------------------------------------------------------------------------
__device__ __forceinline__ void phase_out(char* dsm, int t, int hidx,
                                          const float* __restrict__ bout,
                                          float* __restrict__ out, int cta, int tid) {
    uint32_t sbase = smem_u32(dsm);
    int wid = tid >> 5, lane = tid & 31;
    int mw = wid & 1, nw = wid >> 1;
    int row0 = cta * 32;
    __syncthreads();

    // load h tile (32x128 hi/lo) and WoutT (64x128 hi/lo)
    {
        const __nv_bfloat16* hh = g_hrh[hidx] + (size_t)row0 * 128;
        const __nv_bfloat16* hl = g_hrl[hidx] + (size_t)row0 * 128;
#pragma unroll
        for (int i = 0; i < 2; i++) {
            int idx = tid + i * 256, r = idx >> 4, c = idx & 15;
            cpa16(sbase + OUT_HA  + r * OUT_RSB + c * 16, hh + (size_t)r * 128 + c * 8);
            cpa16(sbase + OUT_HAL + r * OUT_RSB + c * 16, hl + (size_t)r * 128 + c * 8);
        }
#pragma unroll
        for (int i = 0; i < 4; i++) {
            int idx = tid + i * 256, r = idx >> 4, c = idx & 15;
            cpa16(sbase + OUT_WB  + r * OUT_RSB + c * 16, g_WoTh + (size_t)r * 128 + c * 8);
            cpa16(sbase + OUT_WBL + r * OUT_RSB + c * 16, g_WoTl + (size_t)r * 128 + c * 8);
        }
        CP_COMMIT();
    }

    // prefetch Xi + bias while loads fly
    int rA = row0 + mw * 16 + (lane >> 2);
    int cA = nw * 16 + (lane & 3) * 2;
    float2 xi[2][2], bo[2];
#pragma unroll
    for (int nf = 0; nf < 2; nf++) {
        int col = cA + nf * 8;
        xi[nf][0] = *(const float2*)&g_Xi[rA * 64 + col];
        xi[nf][1] = *(const float2*)&g_Xi[(rA + 8) * 64 + col];
        bo[nf] = *(const float2*)&bout[col];
    }

    CP_WAIT0();
    __syncthreads();

    uint32_t aH = sbase + OUT_HA + (uint32_t)(mw * 16 + (lane & 15)) * OUT_RSB + ((lane >> 4) * 16);
    uint32_t aL = aH + (OUT_HAL - OUT_HA);
    uint32_t bH = sbase + OUT_WB
                + (uint32_t)(nw * 16 + (lane & 7) + ((lane >> 4) & 1) * 8) * OUT_RSB
                + (((lane >> 3) & 1) * 16);
    uint32_t bL = bH + (OUT_WBL - OUT_WB);

    float acc[2][4] = {};
#pragma unroll
    for (int ks = 0; ks < 8; ks++) {
        uint32_t ah[4], al[4], bh[4], bl[4];
        ldsm4(ah, aH + ks * 32);
        ldsm4(al, aL + ks * 32);
        ldsm4(bh, bH + ks * 32);
        ldsm4(bl, bL + ks * 32);
        mmabf(acc[0], ah, &bh[0]); mmabf(acc[1], ah, &bh[2]);
        mmabf(acc[0], al, &bh[0]); mmabf(acc[1], al, &bh[2]);
        mmabf(acc[0], ah, &bl[0]); mmabf(acc[1], ah, &bl[2]);
    }

#pragma unroll
    for (int nf = 0; nf < 2; nf++) {
        int col = cA + nf * 8;
        float2 v0 = make_float2(acc[nf][0] + xi[nf][0].x + bo[nf].x,
                                acc[nf][1] + xi[nf][0].y + bo[nf].y);
        float2 v1 = make_float2(acc[nf][2] + xi[nf][1].x + bo[nf].x,
                                acc[nf][3] + xi[nf][1].y + bo[nf].y);
        *(float2*)&g_Xi[rA * 64 + col] = v0;
        *(float2*)&g_Xi[(rA + 8) * 64 + col] = v1;
        *(float2*)&out[(size_t)rA * 4096 + t * 64 + col] = v0;
        *(float2*)&out[(size_t)(rA + 8) * 4096 + t * 64 + col] = v1;
    }
    __syncthreads();
}

// ---------------------------------------------------------------------------
// k_main: persistent kernel, 63 steps, 2 grid barriers per step.
// ---------------------------------------------------------------------------
__global__ void __launch_bounds__(256) k_main(const float* __restrict__ bout,
                                              float* __restrict__ out) {
    extern __shared__ __align__(16) char dsm[];
    int cta = blockIdx.x, tid = threadIdx.x;

    // persistent weight slice for this CTA's gG n-tile
    {
        int n0 = (cta & 3) * 128;
        uint32_t wt = smem_u32(dsm) + SM_WT;
#pragma unroll
        for (int i = 0; i < 16; i++) {
            int idx = tid + i * 256;
            int r = idx >> 5, c = idx & 31;
            cpa16(wt + r * WT_RSB + c * 16,         g_WTh + (size_t)(n0 + r) * 256 + c * 8);
            cpa16(wt + WT_SZ + r * WT_RSB + c * 16, g_WTl + (size_t)(n0 + r) * 256 + c * 8);
        }
        CP_COMMIT();
        CP_WAIT0();
    }
    __syncthreads();

    unsigned gen = 0;
#pragma unroll 1
    for (int t = 1; t < Tc; t++) {
        int hin = (t - 1) & 1, hout = t & 1;
        phase_gH(dsm, hin, cta, tid);
        if (t >= 2) phase_out(dsm, t - 1, hin, bout, out, cta, tid);
        gbar(++gen);
        phase_gG(dsm, hin, hout, cta, tid);
        gbar(++gen);
    }
    phase_out(dsm, Tc - 1, (Tc - 1) & 1, bout, out, cta, tid);
}

// ---------------------------------------------------------------------------
extern "C" void kernel_launch(void* const* d_in, const int* in_sizes, int n_in,
                              void* d_out, int out_size) {
    const float* X    = (const float*)d_in[0];
    const float* A    = (const float*)d_in[1];
    const float* Wse  = (const float*)d_in[2];
    const float* bse  = (const float*)d_in[3];
    const float* Wpe  = (const float*)d_in[4];
    const float* bpe  = (const float*)d_in[5];
    const float* Wii  = (const float*)d_in[6];
    const float* bii  = (const float*)d_in[7];
    const float* Whi  = (const float*)d_in[8];
    const float* bhi  = (const float*)d_in[9];
    const float* Wif  = (const float*)d_in[10];
    const float* bif_ = (const float*)d_in[11];
    const float* Whf  = (const float*)d_in[12];
    const float* bhf  = (const float*)d_in[13];
    const float* Wig  = (const float*)d_in[14];
    const float* big_ = (const float*)d_in[15];
    const float* Whg  = (const float*)d_in[16];
    const float* bhg  = (const float*)d_in[17];
    const float* Wio  = (const float*)d_in[18];
    const float* bio  = (const float*)d_in[19];
    const float* Who  = (const float*)d_in[20];
    const float* bho  = (const float*)d_in[21];
    const float* Wout = (const float*)d_in[22];
    const float* bout = (const float*)d_in[23];
    float* out = (float*)d_out;

    cudaFuncSetAttribute(k_main, cudaFuncAttributeMaxDynamicSharedMemorySize, SM_TOTAL);

    k_dinv<<<Rc, 128>>>(A);
    k_an<<<2048, 256>>>(A);
    k_prep<<<512, 128>>>(Wii, bii, Whi, bhi, Wif, bif_, Whf, bhf,
                         Wig, big_, Whg, bhg, Wio, bio, Who, bho, Wpe, bpe);
    k_prepout<<<64, 128>>>(Wout);
    k_init<<<Rc, 128>>>(X, Wse, bse, out);
    k_ges<<<256, 256>>>();
    k_main<<<NCTA, 256, SM_TOTAL>>>(bout, out);
}